// round 2
// baseline (speedup 1.0000x reference)
#include <cuda_runtime.h>

#define Bq 4
#define Sq 1024
#define Eq 1024
#define Hq 16
#define HDq 64
#define Mtot (Bq*Sq)   // 4096

// Scratch (static device globals: allocation-free)
__device__ float g_Q[Bq*Hq*Sq*HDq];    // [B,H,S,HD]
__device__ float g_K[Bq*Hq*Sq*HDq];
__device__ float g_V[Bq*Hq*Sq*HDq];
__device__ float g_ctx[Bq*Sq*Eq];      // [B,S,E] (concat layout)

// ---------------------------------------------------------------------------
// NT SGEMM: C[M,N] = A[M,K] @ W[N,K]^T, K = N = 1024, M = 4096.
// 128x128 block tile, kstep 8, 256 threads, 8x8 per-thread micro-tile.
// remap=1: scatter C into [B,H,S,HD] layout (for Q/K/V projections).
// remap=0: plain row-major [M,N] store (output projection).
// ---------------------------------------------------------------------------
__global__ void __launch_bounds__(256, 2)
gemm_nt(const float* __restrict__ A, const float* __restrict__ W,
        float* __restrict__ C, int remap, float scale)
{
    __shared__ float As[8][128];
    __shared__ float Bs[8][128];
    const int K = Eq;
    const int t  = threadIdx.x;
    const int tx = t & 15, ty = t >> 4;
    const int arow = t >> 1;          // 0..127
    const int ac4  = (t & 1) * 4;     // 0 or 4

    const float* Ap = A + (size_t)(blockIdx.y * 128 + arow) * K + ac4;
    const float* Wp = W + (size_t)(blockIdx.x * 128 + arow) * K + ac4;

    float acc[8][8];
#pragma unroll
    for (int i = 0; i < 8; ++i)
#pragma unroll
        for (int j = 0; j < 8; ++j) acc[i][j] = 0.f;

    for (int kt = 0; kt < K; kt += 8) {
        float4 av = *(const float4*)(Ap + kt);
        float4 wv = *(const float4*)(Wp + kt);
        __syncthreads();   // previous compute done before smem overwrite
        As[ac4+0][arow] = av.x; As[ac4+1][arow] = av.y;
        As[ac4+2][arow] = av.z; As[ac4+3][arow] = av.w;
        Bs[ac4+0][arow] = wv.x; Bs[ac4+1][arow] = wv.y;
        Bs[ac4+2][arow] = wv.z; Bs[ac4+3][arow] = wv.w;
        __syncthreads();
#pragma unroll
        for (int c = 0; c < 8; ++c) {
            float4 a0 = *(const float4*)&As[c][ty*8];
            float4 a1 = *(const float4*)&As[c][ty*8+4];
            float4 b0 = *(const float4*)&Bs[c][tx*8];
            float4 b1 = *(const float4*)&Bs[c][tx*8+4];
            float a[8] = {a0.x,a0.y,a0.z,a0.w,a1.x,a1.y,a1.z,a1.w};
            float b[8] = {b0.x,b0.y,b0.z,b0.w,b1.x,b1.y,b1.z,b1.w};
#pragma unroll
            for (int i = 0; i < 8; ++i)
#pragma unroll
                for (int j = 0; j < 8; ++j)
                    acc[i][j] = fmaf(a[i], b[j], acc[i][j]);
        }
    }

    if (remap == 0) {
#pragma unroll
        for (int i = 0; i < 8; ++i) {
            size_t m = (size_t)blockIdx.y * 128 + ty*8 + i;
            float* dst = C + m * Eq + blockIdx.x * 128 + tx*8;
            float4 o0 = make_float4(acc[i][0]*scale, acc[i][1]*scale,
                                    acc[i][2]*scale, acc[i][3]*scale);
            float4 o1 = make_float4(acc[i][4]*scale, acc[i][5]*scale,
                                    acc[i][6]*scale, acc[i][7]*scale);
            *(float4*)(dst)     = o0;
            *(float4*)(dst + 4) = o1;
        }
    } else {
        // n -> (h, d); m -> (b, s); dst layout [B,H,S,HD]
        const int n0 = blockIdx.x * 128 + tx*8;
        const int h  = n0 >> 6;
        const int d  = n0 & 63;   // span of 8 stays inside one head (64 % 8 == 0)
#pragma unroll
        for (int i = 0; i < 8; ++i) {
            int m = blockIdx.y * 128 + ty*8 + i;
            int b = m >> 10, s = m & 1023;
            float* dst = C + (((size_t)(b*Hq + h))*Sq + s)*HDq + d;
            float4 o0 = make_float4(acc[i][0]*scale, acc[i][1]*scale,
                                    acc[i][2]*scale, acc[i][3]*scale);
            float4 o1 = make_float4(acc[i][4]*scale, acc[i][5]*scale,
                                    acc[i][6]*scale, acc[i][7]*scale);
            *(float4*)(dst)     = o0;
            *(float4*)(dst + 4) = o1;
        }
    }
}

// ---------------------------------------------------------------------------
// Flash-style attention: one block per (q-tile of 64, head, batch).
// 256 threads as 16 groups x 16 lanes; each thread owns a 4x4 micro-tile.
// Online softmax; P staged in smem; output written in concat layout [B,S,E].
// Scale already folded into Q at projection time.
// ---------------------------------------------------------------------------
#define KPAD 68
#define ATTN_SMEM ((64*64*3 + 64*KPAD) * 4)   // Qs + Vs + Ps (stride 64) + Ks (stride 68)

__global__ void __launch_bounds__(256)
attn_kernel(const float* __restrict__ Q, const float* __restrict__ Kg,
            const float* __restrict__ Vg, float* __restrict__ ctx)
{
    extern __shared__ float smp[];
    float* Qs = smp;              // [64][64]
    float* Ks = Qs + 64*64;       // [64][KPAD]
    float* Vs = Ks + 64*KPAD;     // [64][64]
    float* Ps = Vs + 64*64;       // [64][64]

    const int t  = threadIdx.x;
    const int tx = t & 15;
    const int r0 = (t >> 4) * 4;  // 4 query rows owned by this thread's group
    const int c0 = tx * 4;        // 4 kv cols / 4 head-dims owned by this thread
    const int qb = blockIdx.x, h = blockIdx.y, b = blockIdx.z;

    const float* Qgp = Q  + (((size_t)(b*Hq + h))*Sq + qb*64) * HDq;
    const float* Kgp = Kg + ((size_t)(b*Hq + h))*Sq*HDq;
    const float* Vgp = Vg + ((size_t)(b*Hq + h))*Sq*HDq;

#pragma unroll
    for (int i = t; i < 1024; i += 256)
        ((float4*)Qs)[i] = ((const float4*)Qgp)[i];

    float acc[4][4] = {};
    float mI[4], lI[4];
#pragma unroll
    for (int i = 0; i < 4; ++i) { mI[i] = -1e30f; lI[i] = 0.f; }

    for (int kt = 0; kt < 16; ++kt) {
        __syncthreads();   // previous tile's PV done before K/V overwrite
        const float4* Kt = (const float4*)(Kgp + (size_t)kt*64*64);
        const float4* Vt = (const float4*)(Vgp + (size_t)kt*64*64);
#pragma unroll
        for (int i = t; i < 1024; i += 256) {
            float4 kv = Kt[i];
            int r = i >> 4, cc = (i & 15) << 2;
            *(float4*)(Ks + r*KPAD + cc) = kv;
            ((float4*)Vs)[i] = Vt[i];
        }
        __syncthreads();

        // S = Q @ K^T for this 64x64 tile
        float sc[4][4] = {};
#pragma unroll
        for (int dc = 0; dc < 64; dc += 4) {
            float4 q4[4], k4[4];
#pragma unroll
            for (int i = 0; i < 4; ++i) q4[i] = *(const float4*)(Qs + (r0+i)*64 + dc);
#pragma unroll
            for (int j = 0; j < 4; ++j) k4[j] = *(const float4*)(Ks + (c0+j)*KPAD + dc);
#pragma unroll
            for (int i = 0; i < 4; ++i)
#pragma unroll
                for (int j = 0; j < 4; ++j) {
                    sc[i][j] = fmaf(q4[i].x, k4[j].x, sc[i][j]);
                    sc[i][j] = fmaf(q4[i].y, k4[j].y, sc[i][j]);
                    sc[i][j] = fmaf(q4[i].z, k4[j].z, sc[i][j]);
                    sc[i][j] = fmaf(q4[i].w, k4[j].w, sc[i][j]);
                }
        }

        // Online softmax (row reductions across the 16 lanes of this group)
#pragma unroll
        for (int i = 0; i < 4; ++i) {
            float rm = fmaxf(fmaxf(sc[i][0], sc[i][1]), fmaxf(sc[i][2], sc[i][3]));
#pragma unroll
            for (int off = 8; off; off >>= 1)
                rm = fmaxf(rm, __shfl_xor_sync(0xffffffffu, rm, off, 16));
            float mn    = fmaxf(mI[i], rm);
            float alpha = __expf(mI[i] - mn);
            mI[i] = mn;
            float rs = 0.f;
#pragma unroll
            for (int j = 0; j < 4; ++j) { sc[i][j] = __expf(sc[i][j] - mn); rs += sc[i][j]; }
#pragma unroll
            for (int off = 8; off; off >>= 1)
                rs += __shfl_xor_sync(0xffffffffu, rs, off, 16);
            lI[i] = lI[i]*alpha + rs;
#pragma unroll
            for (int j = 0; j < 4; ++j) acc[i][j] *= alpha;
            *(float4*)(Ps + (r0+i)*64 + c0) =
                make_float4(sc[i][0], sc[i][1], sc[i][2], sc[i][3]);
        }
        __syncthreads();

        // O += P @ V  (this thread accumulates rows r0..r0+3, head-dims c0..c0+3)
#pragma unroll 8
        for (int j = 0; j < 64; ++j) {
            float4 v4 = *(const float4*)(Vs + j*64 + c0);
            float p0 = Ps[(r0+0)*64 + j];
            float p1 = Ps[(r0+1)*64 + j];
            float p2 = Ps[(r0+2)*64 + j];
            float p3 = Ps[(r0+3)*64 + j];
            acc[0][0] = fmaf(p0, v4.x, acc[0][0]); acc[0][1] = fmaf(p0, v4.y, acc[0][1]);
            acc[0][2] = fmaf(p0, v4.z, acc[0][2]); acc[0][3] = fmaf(p0, v4.w, acc[0][3]);
            acc[1][0] = fmaf(p1, v4.x, acc[1][0]); acc[1][1] = fmaf(p1, v4.y, acc[1][1]);
            acc[1][2] = fmaf(p1, v4.z, acc[1][2]); acc[1][3] = fmaf(p1, v4.w, acc[1][3]);
            acc[2][0] = fmaf(p2, v4.x, acc[2][0]); acc[2][1] = fmaf(p2, v4.y, acc[2][1]);
            acc[2][2] = fmaf(p2, v4.z, acc[2][2]); acc[2][3] = fmaf(p2, v4.w, acc[2][3]);
            acc[3][0] = fmaf(p3, v4.x, acc[3][0]); acc[3][1] = fmaf(p3, v4.y, acc[3][1]);
            acc[3][2] = fmaf(p3, v4.z, acc[3][2]); acc[3][3] = fmaf(p3, v4.w, acc[3][3]);
        }
    }

    // Normalize and write concat layout [B, S, E], e = h*64 + d
#pragma unroll
    for (int i = 0; i < 4; ++i) {
        float inv = 1.0f / lI[i];
        float* dst = ctx + ((size_t)b*Sq + qb*64 + r0 + i)*Eq + h*64 + c0;
        *(float4*)dst = make_float4(acc[i][0]*inv, acc[i][1]*inv,
                                    acc[i][2]*inv, acc[i][3]*inv);
    }
}

// ---------------------------------------------------------------------------
extern "C" void kernel_launch(void* const* d_in, const int* in_sizes, int n_in,
                              void* d_out, int out_size)
{
    const float* q  = (const float*)d_in[0];
    const float* k  = (const float*)d_in[1];
    const float* v  = (const float*)d_in[2];
    const float* Wq = (const float*)d_in[3];
    const float* Wk = (const float*)d_in[4];
    const float* Wv = (const float*)d_in[5];
    const float* Wo = (const float*)d_in[6];
    float* out = (float*)d_out;

    float *gQ, *gK, *gV, *gctx;
    cudaGetSymbolAddress((void**)&gQ,   g_Q);
    cudaGetSymbolAddress((void**)&gK,   g_K);
    cudaGetSymbolAddress((void**)&gV,   g_V);
    cudaGetSymbolAddress((void**)&gctx, g_ctx);

    dim3 ggrid(Eq/128, Mtot/128);   // (8, 32)

    // Projections (softmax scale 1/sqrt(64) folded into Q)
    gemm_nt<<<ggrid, 256>>>(q, Wq, gQ, 1, 0.125f);
    gemm_nt<<<ggrid, 256>>>(k, Wk, gK, 1, 1.0f);
    gemm_nt<<<ggrid, 256>>>(v, Wv, gV, 1, 1.0f);

    // Attention
    cudaFuncSetAttribute(attn_kernel, cudaFuncAttributeMaxDynamicSharedMemorySize,
                         ATTN_SMEM);
    attn_kernel<<<dim3(Sq/64, Hq, Bq), 256, ATTN_SMEM>>>(gQ, gK, gV, gctx);

    // Output projection straight into d_out
    gemm_nt<<<ggrid, 256>>>(gctx, Wo, out, 0, 1.0f);
}

// round 4
// speedup vs baseline: 1.2632x; 1.2632x over previous
#include <cuda_runtime.h>
#include <cstdint>

#define Bq 4
#define Sq 1024
#define Eq 1024
#define Hq 16
#define HDq 64
#define Mtot (Bq*Sq)   // 4096

// Scratch (static device globals: allocation-free)
__device__ float g_Q[Bq*Hq*Sq*HDq];    // [B,H,S,HD]
__device__ float g_K[Bq*Hq*Sq*HDq];
__device__ float g_V[Bq*Hq*Sq*HDq];
__device__ float g_ctx[Bq*Sq*Eq];      // [B,S,E] (concat layout)

__device__ __forceinline__ uint32_t f2tf32(float x) {
    uint32_t r;
    asm("cvt.rna.tf32.f32 %0, %1;" : "=r"(r) : "f"(x));
    return r;
}

__device__ __forceinline__ void mma_tf32(float c[4], const uint32_t a[4],
                                         const uint32_t b[2]) {
    asm volatile(
        "mma.sync.aligned.m16n8k8.row.col.f32.tf32.tf32.f32 "
        "{%0,%1,%2,%3}, {%4,%5,%6,%7}, {%8,%9}, {%0,%1,%2,%3};"
        : "+f"(c[0]), "+f"(c[1]), "+f"(c[2]), "+f"(c[3])
        : "r"(a[0]), "r"(a[1]), "r"(a[2]), "r"(a[3]), "r"(b[0]), "r"(b[1]));
}

// ===========================================================================
// tf32 mma.sync NT GEMM: C[M,N] = A[M,K] @ W[N,K]^T, K = 1024.
// Block 128x128, 256 thr = 8 warps (4m x 2n), warp tile 32x64.
// Smem [k][row] with row-stride 136 (conflict-free frag LDS + staging STS).
// Double-buffered 16-float K-chunks, LDG prefetch overlapping MMA.
// remap=1: scatter into [B,H,S,HD]; remap=0: row-major. scale in epilogue.
// ===========================================================================
#define SSTR 136
#define CHUNK_FLOATS (16*SSTR)          // one buffer of one operand
#define GEMM_SMEM (4*CHUNK_FLOATS*4)    // A0,A1,W0,W1 = 69632 bytes
#define NSTAGE 64                       // 1024 / 16

__global__ void __launch_bounds__(256, 2)
gemm_mma(const float* __restrict__ A, const float* __restrict__ W,
         float* __restrict__ C, int remap, float scale)
{
    extern __shared__ float sm[];
    float* As = sm;                     // [2][16][SSTR]
    float* Ws = sm + 2*CHUNK_FLOATS;    // [2][16][SSTR]

    const int tid  = threadIdx.x;
    const int wid  = tid >> 5;
    const int lane = tid & 31;
    const int g    = lane >> 2;         // groupID 0..7
    const int tig  = lane & 3;          // thread-in-group 0..3
    const int wm   = (wid & 3) * 32;    // warp m offset in tile
    const int wn   = (wid >> 2) * 64;   // warp n offset in tile
    const int m0 = blockIdx.y * 128;
    const int n0 = blockIdx.x * 128;

    // staging indices: idx = tid + i*256 -> m = idx&127 (lane-consecutive),
    // kq = idx>>7 (float4 index along k within the 16-float chunk)
    const int sm_row = tid & 127;
    const int kq0    = tid >> 7;        // 0 or 1; second iter adds 2

    float c[2][8][4];
#pragma unroll
    for (int mt = 0; mt < 2; ++mt)
#pragma unroll
        for (int nt = 0; nt < 8; ++nt)
#pragma unroll
            for (int r = 0; r < 4; ++r) c[mt][nt][r] = 0.f;

    const float* Arow = A + (size_t)(m0 + sm_row) * Eq;
    const float* Wrow = W + (size_t)(n0 + sm_row) * Eq;

    float4 ra[2], rw[2];
    // prologue: stage 0
#pragma unroll
    for (int i = 0; i < 2; ++i) {
        int kq = kq0 + 2*i;
        ra[i] = *(const float4*)(Arow + kq*4);
        rw[i] = *(const float4*)(Wrow + kq*4);
    }
#pragma unroll
    for (int i = 0; i < 2; ++i) {
        int kq = kq0 + 2*i;
        float* ad = As + (kq*4)*SSTR + sm_row;
        float* wd = Ws + (kq*4)*SSTR + sm_row;
        ad[0*SSTR] = __uint_as_float(f2tf32(ra[i].x));
        ad[1*SSTR] = __uint_as_float(f2tf32(ra[i].y));
        ad[2*SSTR] = __uint_as_float(f2tf32(ra[i].z));
        ad[3*SSTR] = __uint_as_float(f2tf32(ra[i].w));
        wd[0*SSTR] = __uint_as_float(f2tf32(rw[i].x));
        wd[1*SSTR] = __uint_as_float(f2tf32(rw[i].y));
        wd[2*SSTR] = __uint_as_float(f2tf32(rw[i].z));
        wd[3*SSTR] = __uint_as_float(f2tf32(rw[i].w));
    }
    __syncthreads();

    for (int s = 0; s < NSTAGE; ++s) {
        // prefetch stage s+1 into registers (overlaps MMA below)
        if (s + 1 < NSTAGE) {
            int k0 = (s + 1) * 16;
#pragma unroll
            for (int i = 0; i < 2; ++i) {
                int kq = kq0 + 2*i;
                ra[i] = *(const float4*)(Arow + k0 + kq*4);
                rw[i] = *(const float4*)(Wrow + k0 + kq*4);
            }
        }

        const float* Ab = As + (s & 1) * CHUNK_FLOATS;
        const float* Wb = Ws + (s & 1) * CHUNK_FLOATS;

#pragma unroll
        for (int ks = 0; ks < 16; ks += 8) {
            uint32_t af[2][4], bf[8][2];
#pragma unroll
            for (int mt = 0; mt < 2; ++mt) {
                int mr = wm + mt*16 + g;
                af[mt][0] = __float_as_uint(Ab[(ks+tig  )*SSTR + mr    ]);
                af[mt][1] = __float_as_uint(Ab[(ks+tig  )*SSTR + mr + 8]);
                af[mt][2] = __float_as_uint(Ab[(ks+tig+4)*SSTR + mr    ]);
                af[mt][3] = __float_as_uint(Ab[(ks+tig+4)*SSTR + mr + 8]);
            }
#pragma unroll
            for (int nt = 0; nt < 8; ++nt) {
                int nc = wn + nt*8 + g;
                bf[nt][0] = __float_as_uint(Wb[(ks+tig  )*SSTR + nc]);
                bf[nt][1] = __float_as_uint(Wb[(ks+tig+4)*SSTR + nc]);
            }
#pragma unroll
            for (int mt = 0; mt < 2; ++mt)
#pragma unroll
                for (int nt = 0; nt < 8; ++nt)
                    mma_tf32(c[mt][nt], af[mt], bf[nt]);
        }

        // stage s+1 regs -> other buffer
        if (s + 1 < NSTAGE) {
            float* Ad = As + ((s + 1) & 1) * CHUNK_FLOATS;
            float* Wd = Ws + ((s + 1) & 1) * CHUNK_FLOATS;
#pragma unroll
            for (int i = 0; i < 2; ++i) {
                int kq = kq0 + 2*i;
                float* ad = Ad + (kq*4)*SSTR + sm_row;
                float* wd = Wd + (kq*4)*SSTR + sm_row;
                ad[0*SSTR] = __uint_as_float(f2tf32(ra[i].x));
                ad[1*SSTR] = __uint_as_float(f2tf32(ra[i].y));
                ad[2*SSTR] = __uint_as_float(f2tf32(ra[i].z));
                ad[3*SSTR] = __uint_as_float(f2tf32(ra[i].w));
                wd[0*SSTR] = __uint_as_float(f2tf32(rw[i].x));
                wd[1*SSTR] = __uint_as_float(f2tf32(rw[i].y));
                wd[2*SSTR] = __uint_as_float(f2tf32(rw[i].z));
                wd[3*SSTR] = __uint_as_float(f2tf32(rw[i].w));
            }
        }
        __syncthreads();
    }

    // Epilogue: each thread owns rows {r, r+8} x cols {2tig, 2tig+1} per tile
#pragma unroll
    for (int mt = 0; mt < 2; ++mt) {
#pragma unroll
        for (int nt = 0; nt < 8; ++nt) {
            int row0 = m0 + wm + mt*16 + g;
            int col  = n0 + wn + nt*8 + 2*tig;
#pragma unroll
            for (int half = 0; half < 2; ++half) {
                int row = row0 + half*8;
                float v0 = c[mt][nt][half*2+0] * scale;
                float v1 = c[mt][nt][half*2+1] * scale;
                float* dst;
                if (remap) {
                    int b = row >> 10, s = row & 1023;
                    int h = col >> 6, d = col & 63;
                    dst = C + (((size_t)(b*Hq + h))*Sq + s)*HDq + d;
                } else {
                    dst = C + (size_t)row * Eq + col;
                }
                *(float2*)dst = make_float2(v0, v1);
            }
        }
    }
}

// ---------------------------------------------------------------------------
// Flash-style attention (unchanged — known good)
// ---------------------------------------------------------------------------
#define KPAD 68
#define ATTN_SMEM ((64*64*3 + 64*KPAD) * 4)

__global__ void __launch_bounds__(256)
attn_kernel(const float* __restrict__ Q, const float* __restrict__ Kg,
            const float* __restrict__ Vg, float* __restrict__ ctx)
{
    extern __shared__ float smp[];
    float* Qs = smp;              // [64][64]
    float* Ks = Qs + 64*64;       // [64][KPAD]
    float* Vs = Ks + 64*KPAD;     // [64][64]
    float* Ps = Vs + 64*64;       // [64][64]

    const int t  = threadIdx.x;
    const int tx = t & 15;
    const int r0 = (t >> 4) * 4;
    const int c0 = tx * 4;
    const int qb = blockIdx.x, h = blockIdx.y, b = blockIdx.z;

    const float* Qgp = Q  + (((size_t)(b*Hq + h))*Sq + qb*64) * HDq;
    const float* Kgp = Kg + ((size_t)(b*Hq + h))*Sq*HDq;
    const float* Vgp = Vg + ((size_t)(b*Hq + h))*Sq*HDq;

#pragma unroll
    for (int i = t; i < 1024; i += 256)
        ((float4*)Qs)[i] = ((const float4*)Qgp)[i];

    float acc[4][4] = {};
    float mI[4], lI[4];
#pragma unroll
    for (int i = 0; i < 4; ++i) { mI[i] = -1e30f; lI[i] = 0.f; }

    for (int kt = 0; kt < 16; ++kt) {
        __syncthreads();
        const float4* Kt = (const float4*)(Kgp + (size_t)kt*64*64);
        const float4* Vt = (const float4*)(Vgp + (size_t)kt*64*64);
#pragma unroll
        for (int i = t; i < 1024; i += 256) {
            float4 kv = Kt[i];
            int r = i >> 4, cc = (i & 15) << 2;
            *(float4*)(Ks + r*KPAD + cc) = kv;
            ((float4*)Vs)[i] = Vt[i];
        }
        __syncthreads();

        float sc[4][4] = {};
#pragma unroll
        for (int dc = 0; dc < 64; dc += 4) {
            float4 q4[4], k4[4];
#pragma unroll
            for (int i = 0; i < 4; ++i) q4[i] = *(const float4*)(Qs + (r0+i)*64 + dc);
#pragma unroll
            for (int j = 0; j < 4; ++j) k4[j] = *(const float4*)(Ks + (c0+j)*KPAD + dc);
#pragma unroll
            for (int i = 0; i < 4; ++i)
#pragma unroll
                for (int j = 0; j < 4; ++j) {
                    sc[i][j] = fmaf(q4[i].x, k4[j].x, sc[i][j]);
                    sc[i][j] = fmaf(q4[i].y, k4[j].y, sc[i][j]);
                    sc[i][j] = fmaf(q4[i].z, k4[j].z, sc[i][j]);
                    sc[i][j] = fmaf(q4[i].w, k4[j].w, sc[i][j]);
                }
        }

#pragma unroll
        for (int i = 0; i < 4; ++i) {
            float rm = fmaxf(fmaxf(sc[i][0], sc[i][1]), fmaxf(sc[i][2], sc[i][3]));
#pragma unroll
            for (int off = 8; off; off >>= 1)
                rm = fmaxf(rm, __shfl_xor_sync(0xffffffffu, rm, off, 16));
            float mn    = fmaxf(mI[i], rm);
            float alpha = __expf(mI[i] - mn);
            mI[i] = mn;
            float rs = 0.f;
#pragma unroll
            for (int j = 0; j < 4; ++j) { sc[i][j] = __expf(sc[i][j] - mn); rs += sc[i][j]; }
#pragma unroll
            for (int off = 8; off; off >>= 1)
                rs += __shfl_xor_sync(0xffffffffu, rs, off, 16);
            lI[i] = lI[i]*alpha + rs;
#pragma unroll
            for (int j = 0; j < 4; ++j) acc[i][j] *= alpha;
            *(float4*)(Ps + (r0+i)*64 + c0) =
                make_float4(sc[i][0], sc[i][1], sc[i][2], sc[i][3]);
        }
        __syncthreads();

#pragma unroll 8
        for (int j = 0; j < 64; ++j) {
            float4 v4 = *(const float4*)(Vs + j*64 + c0);
            float p0 = Ps[(r0+0)*64 + j];
            float p1 = Ps[(r0+1)*64 + j];
            float p2 = Ps[(r0+2)*64 + j];
            float p3 = Ps[(r0+3)*64 + j];
            acc[0][0] = fmaf(p0, v4.x, acc[0][0]); acc[0][1] = fmaf(p0, v4.y, acc[0][1]);
            acc[0][2] = fmaf(p0, v4.z, acc[0][2]); acc[0][3] = fmaf(p0, v4.w, acc[0][3]);
            acc[1][0] = fmaf(p1, v4.x, acc[1][0]); acc[1][1] = fmaf(p1, v4.y, acc[1][1]);
            acc[1][2] = fmaf(p1, v4.z, acc[1][2]); acc[1][3] = fmaf(p1, v4.w, acc[1][3]);
            acc[2][0] = fmaf(p2, v4.x, acc[2][0]); acc[2][1] = fmaf(p2, v4.y, acc[2][1]);
            acc[2][2] = fmaf(p2, v4.z, acc[2][2]); acc[2][3] = fmaf(p2, v4.w, acc[2][3]);
            acc[3][0] = fmaf(p3, v4.x, acc[3][0]); acc[3][1] = fmaf(p3, v4.y, acc[3][1]);
            acc[3][2] = fmaf(p3, v4.z, acc[3][2]); acc[3][3] = fmaf(p3, v4.w, acc[3][3]);
        }
    }

#pragma unroll
    for (int i = 0; i < 4; ++i) {
        float inv = 1.0f / lI[i];
        float* dst = ctx + ((size_t)b*Sq + qb*64 + r0 + i)*Eq + h*64 + c0;
        *(float4*)dst = make_float4(acc[i][0]*inv, acc[i][1]*inv,
                                    acc[i][2]*inv, acc[i][3]*inv);
    }
}

// ---------------------------------------------------------------------------
extern "C" void kernel_launch(void* const* d_in, const int* in_sizes, int n_in,
                              void* d_out, int out_size)
{
    const float* q  = (const float*)d_in[0];
    const float* k  = (const float*)d_in[1];
    const float* v  = (const float*)d_in[2];
    const float* Wq = (const float*)d_in[3];
    const float* Wk = (const float*)d_in[4];
    const float* Wv = (const float*)d_in[5];
    const float* Wo = (const float*)d_in[6];
    float* out = (float*)d_out;

    float *gQ, *gK, *gV, *gctx;
    cudaGetSymbolAddress((void**)&gQ,   g_Q);
    cudaGetSymbolAddress((void**)&gK,   g_K);
    cudaGetSymbolAddress((void**)&gV,   g_V);
    cudaGetSymbolAddress((void**)&gctx, g_ctx);

    cudaFuncSetAttribute(gemm_mma, cudaFuncAttributeMaxDynamicSharedMemorySize,
                         GEMM_SMEM);
    cudaFuncSetAttribute(attn_kernel, cudaFuncAttributeMaxDynamicSharedMemorySize,
                         ATTN_SMEM);

    dim3 ggrid(Eq/128, Mtot/128);   // (8, 32) = 256 CTAs, occ 2 -> one wave

    // Projections (softmax scale 1/sqrt(64) folded into Q epilogue)
    gemm_mma<<<ggrid, 256, GEMM_SMEM>>>(q, Wq, gQ, 1, 0.125f);
    gemm_mma<<<ggrid, 256, GEMM_SMEM>>>(k, Wk, gK, 1, 1.0f);
    gemm_mma<<<ggrid, 256, GEMM_SMEM>>>(v, Wv, gV, 1, 1.0f);

    // Attention
    attn_kernel<<<dim3(Sq/64, Hq, Bq), 256, ATTN_SMEM>>>(gQ, gK, gV, gctx);

    // Output projection straight into d_out
    gemm_mma<<<ggrid, 256, GEMM_SMEM>>>(gctx, Wo, out, 0, 1.0f);
}

// round 5
// speedup vs baseline: 2.3412x; 1.8534x over previous
#include <cuda_runtime.h>
#include <cstdint>

#define Bq 4
#define Sq 1024
#define Eq 1024
#define Hq 16
#define HDq 64
#define Mtot (Bq*Sq)   // 4096

// Scratch (static device globals: allocation-free)
__device__ float g_Q[Bq*Hq*Sq*HDq];    // [B,H,S,HD]
__device__ float g_K[Bq*Hq*Sq*HDq];
__device__ float g_V[Bq*Hq*Sq*HDq];
__device__ float g_ctx[Bq*Sq*Eq];      // [B,S,E] (concat layout)

__device__ __forceinline__ uint32_t f2tf32(float x) {
    uint32_t r;
    asm("cvt.rna.tf32.f32 %0, %1;" : "=r"(r) : "f"(x));
    return r;
}

__device__ __forceinline__ void mma_tf32(float c[4], const uint32_t a[4],
                                         const uint32_t b[2]) {
    asm volatile(
        "mma.sync.aligned.m16n8k8.row.col.f32.tf32.tf32.f32 "
        "{%0,%1,%2,%3}, {%4,%5,%6,%7}, {%8,%9}, {%0,%1,%2,%3};"
        : "+f"(c[0]), "+f"(c[1]), "+f"(c[2]), "+f"(c[3])
        : "r"(a[0]), "r"(a[1]), "r"(a[2]), "r"(a[3]), "r"(b[0]), "r"(b[1]));
}

// ===========================================================================
// tf32 mma.sync NT GEMM (unchanged from R4 — known good)
// ===========================================================================
#define SSTR 136
#define CHUNK_FLOATS (16*SSTR)
#define GEMM_SMEM (4*CHUNK_FLOATS*4)
#define NSTAGE 64

__global__ void __launch_bounds__(256, 2)
gemm_mma(const float* __restrict__ A, const float* __restrict__ W,
         float* __restrict__ C, int remap, float scale)
{
    extern __shared__ float sm[];
    float* As = sm;
    float* Ws = sm + 2*CHUNK_FLOATS;

    const int tid  = threadIdx.x;
    const int wid  = tid >> 5;
    const int lane = tid & 31;
    const int g    = lane >> 2;
    const int tig  = lane & 3;
    const int wm   = (wid & 3) * 32;
    const int wn   = (wid >> 2) * 64;
    const int m0 = blockIdx.y * 128;
    const int n0 = blockIdx.x * 128;

    const int sm_row = tid & 127;
    const int kq0    = tid >> 7;

    float c[2][8][4];
#pragma unroll
    for (int mt = 0; mt < 2; ++mt)
#pragma unroll
        for (int nt = 0; nt < 8; ++nt)
#pragma unroll
            for (int r = 0; r < 4; ++r) c[mt][nt][r] = 0.f;

    const float* Arow = A + (size_t)(m0 + sm_row) * Eq;
    const float* Wrow = W + (size_t)(n0 + sm_row) * Eq;

    float4 ra[2], rw[2];
#pragma unroll
    for (int i = 0; i < 2; ++i) {
        int kq = kq0 + 2*i;
        ra[i] = *(const float4*)(Arow + kq*4);
        rw[i] = *(const float4*)(Wrow + kq*4);
    }
#pragma unroll
    for (int i = 0; i < 2; ++i) {
        int kq = kq0 + 2*i;
        float* ad = As + (kq*4)*SSTR + sm_row;
        float* wd = Ws + (kq*4)*SSTR + sm_row;
        ad[0*SSTR] = __uint_as_float(f2tf32(ra[i].x));
        ad[1*SSTR] = __uint_as_float(f2tf32(ra[i].y));
        ad[2*SSTR] = __uint_as_float(f2tf32(ra[i].z));
        ad[3*SSTR] = __uint_as_float(f2tf32(ra[i].w));
        wd[0*SSTR] = __uint_as_float(f2tf32(rw[i].x));
        wd[1*SSTR] = __uint_as_float(f2tf32(rw[i].y));
        wd[2*SSTR] = __uint_as_float(f2tf32(rw[i].z));
        wd[3*SSTR] = __uint_as_float(f2tf32(rw[i].w));
    }
    __syncthreads();

    for (int s = 0; s < NSTAGE; ++s) {
        if (s + 1 < NSTAGE) {
            int k0 = (s + 1) * 16;
#pragma unroll
            for (int i = 0; i < 2; ++i) {
                int kq = kq0 + 2*i;
                ra[i] = *(const float4*)(Arow + k0 + kq*4);
                rw[i] = *(const float4*)(Wrow + k0 + kq*4);
            }
        }

        const float* Ab = As + (s & 1) * CHUNK_FLOATS;
        const float* Wb = Ws + (s & 1) * CHUNK_FLOATS;

#pragma unroll
        for (int ks = 0; ks < 16; ks += 8) {
            uint32_t af[2][4], bf[8][2];
#pragma unroll
            for (int mt = 0; mt < 2; ++mt) {
                int mr = wm + mt*16 + g;
                af[mt][0] = __float_as_uint(Ab[(ks+tig  )*SSTR + mr    ]);
                af[mt][1] = __float_as_uint(Ab[(ks+tig  )*SSTR + mr + 8]);
                af[mt][2] = __float_as_uint(Ab[(ks+tig+4)*SSTR + mr    ]);
                af[mt][3] = __float_as_uint(Ab[(ks+tig+4)*SSTR + mr + 8]);
            }
#pragma unroll
            for (int nt = 0; nt < 8; ++nt) {
                int nc = wn + nt*8 + g;
                bf[nt][0] = __float_as_uint(Wb[(ks+tig  )*SSTR + nc]);
                bf[nt][1] = __float_as_uint(Wb[(ks+tig+4)*SSTR + nc]);
            }
#pragma unroll
            for (int mt = 0; mt < 2; ++mt)
#pragma unroll
                for (int nt = 0; nt < 8; ++nt)
                    mma_tf32(c[mt][nt], af[mt], bf[nt]);
        }

        if (s + 1 < NSTAGE) {
            float* Ad = As + ((s + 1) & 1) * CHUNK_FLOATS;
            float* Wd = Ws + ((s + 1) & 1) * CHUNK_FLOATS;
#pragma unroll
            for (int i = 0; i < 2; ++i) {
                int kq = kq0 + 2*i;
                float* ad = Ad + (kq*4)*SSTR + sm_row;
                float* wd = Wd + (kq*4)*SSTR + sm_row;
                ad[0*SSTR] = __uint_as_float(f2tf32(ra[i].x));
                ad[1*SSTR] = __uint_as_float(f2tf32(ra[i].y));
                ad[2*SSTR] = __uint_as_float(f2tf32(ra[i].z));
                ad[3*SSTR] = __uint_as_float(f2tf32(ra[i].w));
                wd[0*SSTR] = __uint_as_float(f2tf32(rw[i].x));
                wd[1*SSTR] = __uint_as_float(f2tf32(rw[i].y));
                wd[2*SSTR] = __uint_as_float(f2tf32(rw[i].z));
                wd[3*SSTR] = __uint_as_float(f2tf32(rw[i].w));
            }
        }
        __syncthreads();
    }

#pragma unroll
    for (int mt = 0; mt < 2; ++mt) {
#pragma unroll
        for (int nt = 0; nt < 8; ++nt) {
            int row0 = m0 + wm + mt*16 + g;
            int col  = n0 + wn + nt*8 + 2*tig;
#pragma unroll
            for (int half = 0; half < 2; ++half) {
                int row = row0 + half*8;
                float v0 = c[mt][nt][half*2+0] * scale;
                float v1 = c[mt][nt][half*2+1] * scale;
                float* dst;
                if (remap) {
                    int b = row >> 10, s = row & 1023;
                    int h = col >> 6, d = col & 63;
                    dst = C + (((size_t)(b*Hq + h))*Sq + s)*HDq + d;
                } else {
                    dst = C + (size_t)row * Eq + col;
                }
                *(float2*)dst = make_float2(v0, v1);
            }
        }
    }
}

// ===========================================================================
// tf32 mma.sync flash attention.
// Block = 128 q rows x (head, batch) -> grid (8, 16, 4). 8 warps x 16 q rows.
// Q tf32 fragments live in registers for the whole kernel.
// Per 64-kv tile: stage K/V (tf32) -> QK^T mma -> online softmax on C frags
// -> P (tf32) to per-warp smem -> PV mma. Output to ctx [B,S,E].
// smem: Ks[64][68], Vs[64][72], Ps[8][16][68] (Q staged in Ps region first).
// ===========================================================================
#define KS_STR 68
#define VS_STR 72
#define PS_STR 68
#define ATTN_SMEM ((64*KS_STR + 64*VS_STR + 8*16*PS_STR) * 4)   // 70656

__global__ void __launch_bounds__(256, 2)
attn_mma(const float* __restrict__ Qg, const float* __restrict__ Kg,
         const float* __restrict__ Vg, float* __restrict__ ctx)
{
    extern __shared__ float smp[];
    float* Ks = smp;                        // [64][68]
    float* Vs = Ks + 64*KS_STR;             // [64][72]
    float* Ps = Vs + 64*VS_STR;             // [8][16][68]
    uint32_t* KsU = (uint32_t*)Ks;
    uint32_t* VsU = (uint32_t*)Vs;
    uint32_t* PsU = (uint32_t*)Ps;

    const int tid  = threadIdx.x;
    const int w    = tid >> 5;
    const int lane = tid & 31;
    const int g    = lane >> 2;
    const int tig  = lane & 3;
    const int qb = blockIdx.x, h = blockIdx.y, b = blockIdx.z;

    const float* Qp = Qg + (((size_t)(b*Hq + h))*Sq + qb*128) * HDq;
    const float* Kp = Kg + ((size_t)(b*Hq + h))*Sq*HDq;
    const float* Vp = Vg + ((size_t)(b*Hq + h))*Sq*HDq;

    // ---- Stage Q (tf32) into Ps region [128][68], then load fragments ----
    {
        const float4* Q4 = (const float4*)Qp;
#pragma unroll
        for (int i = 0; i < 8; ++i) {
            int idx = tid + i*256;            // 2048 float4
            int r = idx >> 4, c4 = (idx & 15) * 4;
            float4 v = Q4[idx];
            uint32_t* d = PsU + r*PS_STR + c4;
            d[0] = f2tf32(v.x); d[1] = f2tf32(v.y);
            d[2] = f2tf32(v.z); d[3] = f2tf32(v.w);
        }
    }
    __syncthreads();

    uint32_t qf[8][4];
    {
        const uint32_t* q0 = PsU + (w*16 + g    )*PS_STR;
        const uint32_t* q1 = PsU + (w*16 + g + 8)*PS_STR;
#pragma unroll
        for (int ks = 0; ks < 8; ++ks) {
            qf[ks][0] = q0[ks*8 + tig];
            qf[ks][1] = q1[ks*8 + tig];
            qf[ks][2] = q0[ks*8 + tig + 4];
            qf[ks][3] = q1[ks*8 + tig + 4];
        }
    }
    __syncthreads();   // all q-frag reads done before Ps is reused for P

    float acc[8][4];
#pragma unroll
    for (int n = 0; n < 8; ++n)
#pragma unroll
        for (int r = 0; r < 4; ++r) acc[n][r] = 0.f;
    float m0 = -1e30f, m1 = -1e30f, l0 = 0.f, l1 = 0.f;

    uint32_t* Pw = PsU + w*16*PS_STR;

    for (int kt = 0; kt < 16; ++kt) {
        __syncthreads();   // previous PV (Vs) / P frag reads done
        {
            const float4* Kt = (const float4*)(Kp + (size_t)kt*64*64);
            const float4* Vt = (const float4*)(Vp + (size_t)kt*64*64);
#pragma unroll
            for (int i = 0; i < 4; ++i) {
                int idx = tid + i*256;       // 1024 float4 each
                int r = idx >> 4, c4 = (idx & 15) * 4;
                float4 kv = Kt[idx];
                uint32_t* kd = KsU + r*KS_STR + c4;
                kd[0] = f2tf32(kv.x); kd[1] = f2tf32(kv.y);
                kd[2] = f2tf32(kv.z); kd[3] = f2tf32(kv.w);
                float4 vv = Vt[idx];
                uint32_t* vd = VsU + r*VS_STR + c4;
                vd[0] = f2tf32(vv.x); vd[1] = f2tf32(vv.y);
                vd[2] = f2tf32(vv.z); vd[3] = f2tf32(vv.w);
            }
        }
        __syncthreads();

        // ---- S = Q @ K^T (rows w*16+{g,g+8}, cols = kv) ----
        float sc[8][4];
#pragma unroll
        for (int n = 0; n < 8; ++n) {
#pragma unroll
            for (int r = 0; r < 4; ++r) sc[n][r] = 0.f;
            const uint32_t* kr = KsU + (n*8 + g)*KS_STR;
#pragma unroll
            for (int ks = 0; ks < 8; ++ks) {
                uint32_t bf[2] = { kr[ks*8 + tig], kr[ks*8 + tig + 4] };
                mma_tf32(sc[n], qf[ks], bf);
            }
        }

        // ---- online softmax (two rows per thread) ----
        {
            float mx0 = -1e30f, mx1 = -1e30f;
#pragma unroll
            for (int n = 0; n < 8; ++n) {
                mx0 = fmaxf(mx0, fmaxf(sc[n][0], sc[n][1]));
                mx1 = fmaxf(mx1, fmaxf(sc[n][2], sc[n][3]));
            }
            mx0 = fmaxf(mx0, __shfl_xor_sync(0xffffffffu, mx0, 1));
            mx0 = fmaxf(mx0, __shfl_xor_sync(0xffffffffu, mx0, 2));
            mx1 = fmaxf(mx1, __shfl_xor_sync(0xffffffffu, mx1, 1));
            mx1 = fmaxf(mx1, __shfl_xor_sync(0xffffffffu, mx1, 2));
            float mn0 = fmaxf(m0, mx0), mn1 = fmaxf(m1, mx1);
            float a0 = __expf(m0 - mn0), a1 = __expf(m1 - mn1);
            m0 = mn0; m1 = mn1;
            float rs0 = 0.f, rs1 = 0.f;
#pragma unroll
            for (int n = 0; n < 8; ++n) {
                sc[n][0] = __expf(sc[n][0] - mn0);
                sc[n][1] = __expf(sc[n][1] - mn0);
                sc[n][2] = __expf(sc[n][2] - mn1);
                sc[n][3] = __expf(sc[n][3] - mn1);
                rs0 += sc[n][0] + sc[n][1];
                rs1 += sc[n][2] + sc[n][3];
            }
            rs0 += __shfl_xor_sync(0xffffffffu, rs0, 1);
            rs0 += __shfl_xor_sync(0xffffffffu, rs0, 2);
            rs1 += __shfl_xor_sync(0xffffffffu, rs1, 1);
            rs1 += __shfl_xor_sync(0xffffffffu, rs1, 2);
            l0 = l0*a0 + rs0;
            l1 = l1*a1 + rs1;
#pragma unroll
            for (int n = 0; n < 8; ++n) {
                acc[n][0] *= a0; acc[n][1] *= a0;
                acc[n][2] *= a1; acc[n][3] *= a1;
            }
        }

        // ---- P (tf32) -> per-warp smem ----
#pragma unroll
        for (int n = 0; n < 8; ++n) {
            uint32_t* p0 = Pw + g*PS_STR + n*8 + 2*tig;
            uint32_t* p1 = Pw + (g+8)*PS_STR + n*8 + 2*tig;
            p0[0] = f2tf32(sc[n][0]); p0[1] = f2tf32(sc[n][1]);
            p1[0] = f2tf32(sc[n][2]); p1[1] = f2tf32(sc[n][3]);
        }
        __syncwarp();

        // ---- O += P @ V ----
        uint32_t af[8][4];
#pragma unroll
        for (int ks = 0; ks < 8; ++ks) {
            af[ks][0] = Pw[ g   *PS_STR + ks*8 + tig];
            af[ks][1] = Pw[(g+8)*PS_STR + ks*8 + tig];
            af[ks][2] = Pw[ g   *PS_STR + ks*8 + tig + 4];
            af[ks][3] = Pw[(g+8)*PS_STR + ks*8 + tig + 4];
        }
#pragma unroll
        for (int n = 0; n < 8; ++n) {
#pragma unroll
            for (int ks = 0; ks < 8; ++ks) {
                uint32_t bf[2] = { VsU[(ks*8 + tig  )*VS_STR + n*8 + g],
                                   VsU[(ks*8 + tig+4)*VS_STR + n*8 + g] };
                mma_tf32(acc[n], af[ks], bf);
            }
        }
    }

    // ---- normalize and write ctx [B,S,E] ----
    float inv0 = 1.0f / l0, inv1 = 1.0f / l1;
    int row0 = qb*128 + w*16 + g;
#pragma unroll
    for (int n = 0; n < 8; ++n) {
        int e = h*64 + n*8 + 2*tig;
        float* d0 = ctx + ((size_t)b*Sq + row0    )*Eq + e;
        float* d1 = ctx + ((size_t)b*Sq + row0 + 8)*Eq + e;
        *(float2*)d0 = make_float2(acc[n][0]*inv0, acc[n][1]*inv0);
        *(float2*)d1 = make_float2(acc[n][2]*inv1, acc[n][3]*inv1);
    }
}

// ---------------------------------------------------------------------------
extern "C" void kernel_launch(void* const* d_in, const int* in_sizes, int n_in,
                              void* d_out, int out_size)
{
    const float* q  = (const float*)d_in[0];
    const float* k  = (const float*)d_in[1];
    const float* v  = (const float*)d_in[2];
    const float* Wq = (const float*)d_in[3];
    const float* Wk = (const float*)d_in[4];
    const float* Wv = (const float*)d_in[5];
    const float* Wo = (const float*)d_in[6];
    float* out = (float*)d_out;

    float *gQ, *gK, *gV, *gctx;
    cudaGetSymbolAddress((void**)&gQ,   g_Q);
    cudaGetSymbolAddress((void**)&gK,   g_K);
    cudaGetSymbolAddress((void**)&gV,   g_V);
    cudaGetSymbolAddress((void**)&gctx, g_ctx);

    cudaFuncSetAttribute(gemm_mma, cudaFuncAttributeMaxDynamicSharedMemorySize,
                         GEMM_SMEM);
    cudaFuncSetAttribute(attn_mma, cudaFuncAttributeMaxDynamicSharedMemorySize,
                         ATTN_SMEM);

    dim3 ggrid(Eq/128, Mtot/128);   // (8, 32) = 256 CTAs

    gemm_mma<<<ggrid, 256, GEMM_SMEM>>>(q, Wq, gQ, 1, 0.125f);
    gemm_mma<<<ggrid, 256, GEMM_SMEM>>>(k, Wk, gK, 1, 1.0f);
    gemm_mma<<<ggrid, 256, GEMM_SMEM>>>(v, Wv, gV, 1, 1.0f);

    attn_mma<<<dim3(Sq/128, Hq, Bq), 256, ATTN_SMEM>>>(gQ, gK, gV, gctx);

    gemm_mma<<<ggrid, 256, GEMM_SMEM>>>(gctx, Wo, out, 0, 1.0f);
}

// round 6
// speedup vs baseline: 3.5826x; 1.5302x over previous
#include <cuda_runtime.h>
#include <cstdint>

#define Bq 4
#define Sq 1024
#define Eq 1024
#define Hq 16
#define HDq 64
#define Mtot (Bq*Sq)   // 4096

// Scratch (static device globals: allocation-free)
__device__ float g_Q[Bq*Hq*Sq*HDq];    // [B,H,S,HD]
__device__ float g_K[Bq*Hq*Sq*HDq];
__device__ float g_V[Bq*Hq*Sq*HDq];
__device__ float g_ctx[Bq*Sq*Eq];      // [B,S,E] (concat layout)

__device__ __forceinline__ uint32_t f2tf32(float x) {
    uint32_t r;
    asm("cvt.rna.tf32.f32 %0, %1;" : "=r"(r) : "f"(x));
    return r;
}

__device__ __forceinline__ uint32_t smem_u32(const void* p) {
    uint32_t a;
    asm("{ .reg .u64 t; cvta.to.shared.u64 t, %1; cvt.u32.u64 %0, t; }"
        : "=r"(a) : "l"(p));
    return a;
}

__device__ __forceinline__ void cp_async16(uint32_t dst, const void* src) {
    asm volatile("cp.async.cg.shared.global [%0], [%1], 16;"
                 :: "r"(dst), "l"(src));
}
#define CP_COMMIT()  asm volatile("cp.async.commit_group;" ::: "memory")
#define CP_WAIT2()   asm volatile("cp.async.wait_group 2;" ::: "memory")

__device__ __forceinline__ void mma_tf32(float c[4], const uint32_t a[4],
                                         const uint32_t b[2]) {
    asm volatile(
        "mma.sync.aligned.m16n8k8.row.col.f32.tf32.tf32.f32 "
        "{%0,%1,%2,%3}, {%4,%5,%6,%7}, {%8,%9}, {%0,%1,%2,%3};"
        : "+f"(c[0]), "+f"(c[1]), "+f"(c[2]), "+f"(c[3])
        : "r"(a[0]), "r"(a[1]), "r"(a[2]), "r"(a[3]), "r"(b[0]), "r"(b[1]));
}

// ===========================================================================
// tf32 mma.sync NT GEMM with cp.async 4-stage pipeline.
// C[M,N] = A[M,K] @ W[N,K]^T, K = 1024. Block 128x128, 8 warps (4m x 2n),
// warp tile 32x64. Smem stage: [row][k] fp32, stride 20 (conflict-free frag
// LDS for lanes (g,tig): g*20+tig distinct mod 32). tf32 cvt at frag load.
// remap=1: scatter into [B,H,S,HD]; remap=0: row-major. scale in epilogue.
// ===========================================================================
#define RSTR 20
#define STAGE_FLOATS (128*RSTR)            // 2560 floats per operand-stage
#define GEMM_SMEM (8*STAGE_FLOATS*4)       // 4 stages x (A,W) = 81920 B
#define NSTAGE 64                          // 1024 / 16

__global__ void __launch_bounds__(256, 2)
gemm_mma(const float* __restrict__ A, const float* __restrict__ W,
         float* __restrict__ C, int remap, float scale)
{
    extern __shared__ float sm[];
    // layout: stage p: A at sm + p*2*STAGE_FLOATS, W at +STAGE_FLOATS
    const uint32_t smb = smem_u32(sm);

    const int tid  = threadIdx.x;
    const int wid  = tid >> 5;
    const int lane = tid & 31;
    const int g    = lane >> 2;
    const int tig  = lane & 3;
    const int wm   = (wid & 3) * 32;
    const int wn   = (wid >> 2) * 64;
    const int m0 = blockIdx.y * 128;
    const int n0 = blockIdx.x * 128;

    // cp.async mapping: idx in [0,512): row = idx>>2, kc = (idx&3)*4
    const int r_a = tid >> 2;            // rows for idx = tid
    const int kc_a = (tid & 3) * 4;
    const int r_b = (tid + 256) >> 2;    // rows for idx = tid+256
    const int kc_b = ((tid + 256) & 3) * 4;

    const float* Aga = A + (size_t)(m0 + r_a) * Eq + kc_a;
    const float* Agb = A + (size_t)(m0 + r_b) * Eq + kc_b;
    const float* Wga = W + (size_t)(n0 + r_a) * Eq + kc_a;
    const float* Wgb = W + (size_t)(n0 + r_b) * Eq + kc_b;
    const uint32_t sa_a = smb + (r_a*RSTR + kc_a) * 4;
    const uint32_t sa_b = smb + (r_b*RSTR + kc_b) * 4;
    const uint32_t sw_a = sa_a + STAGE_FLOATS * 4;
    const uint32_t sw_b = sa_b + STAGE_FLOATS * 4;

    float c[2][8][4];
#pragma unroll
    for (int mt = 0; mt < 2; ++mt)
#pragma unroll
        for (int nt = 0; nt < 8; ++nt)
#pragma unroll
            for (int r = 0; r < 4; ++r) c[mt][nt][r] = 0.f;

    // prologue: stages 0..2
#pragma unroll
    for (int p = 0; p < 3; ++p) {
        uint32_t so = (uint32_t)(p * 2 * STAGE_FLOATS * 4);
        int k0 = p * 16;
        cp_async16(sa_a + so, Aga + k0);
        cp_async16(sa_b + so, Agb + k0);
        cp_async16(sw_a + so, Wga + k0);
        cp_async16(sw_b + so, Wgb + k0);
        CP_COMMIT();
    }

    for (int s = 0; s < NSTAGE; ++s) {
        CP_WAIT2();          // stage s resident (s+1, s+2 may be in flight)
        __syncthreads();     // stage s visible; MMA(s-1) retired by all warps

        // issue stage s+3 into buffer (s+3)&3 == (s-1)&3 (reads retired)
        if (s + 3 < NSTAGE) {
            uint32_t so = (uint32_t)(((s + 3) & 3) * 2 * STAGE_FLOATS * 4);
            int k0 = (s + 3) * 16;
            cp_async16(sa_a + so, Aga + k0);
            cp_async16(sa_b + so, Agb + k0);
            cp_async16(sw_a + so, Wga + k0);
            cp_async16(sw_b + so, Wgb + k0);
        }
        CP_COMMIT();         // always commit: 3 groups pending at loop top

        const float* Ab = sm + (s & 3) * 2 * STAGE_FLOATS;
        const float* Wb = Ab + STAGE_FLOATS;

#pragma unroll
        for (int ks = 0; ks < 16; ks += 8) {
            uint32_t af[2][4], bf[8][2];
#pragma unroll
            for (int mt = 0; mt < 2; ++mt) {
                const float* a0 = Ab + (wm + mt*16 + g) * RSTR + ks;
                const float* a1 = a0 + 8 * RSTR;
                af[mt][0] = f2tf32(a0[tig]);
                af[mt][1] = f2tf32(a1[tig]);
                af[mt][2] = f2tf32(a0[tig + 4]);
                af[mt][3] = f2tf32(a1[tig + 4]);
            }
#pragma unroll
            for (int nt = 0; nt < 8; ++nt) {
                const float* b0 = Wb + (wn + nt*8 + g) * RSTR + ks;
                bf[nt][0] = f2tf32(b0[tig]);
                bf[nt][1] = f2tf32(b0[tig + 4]);
            }
#pragma unroll
            for (int mt = 0; mt < 2; ++mt)
#pragma unroll
                for (int nt = 0; nt < 8; ++nt)
                    mma_tf32(c[mt][nt], af[mt], bf[nt]);
        }
    }

    // Epilogue: each thread owns rows {g, g+8} x cols {2tig, 2tig+1} per tile
#pragma unroll
    for (int mt = 0; mt < 2; ++mt) {
#pragma unroll
        for (int nt = 0; nt < 8; ++nt) {
            int row0 = m0 + wm + mt*16 + g;
            int col  = n0 + wn + nt*8 + 2*tig;
#pragma unroll
            for (int half = 0; half < 2; ++half) {
                int row = row0 + half*8;
                float v0 = c[mt][nt][half*2+0] * scale;
                float v1 = c[mt][nt][half*2+1] * scale;
                float* dst;
                if (remap) {
                    int b = row >> 10, s = row & 1023;
                    int h = col >> 6, d = col & 63;
                    dst = C + (((size_t)(b*Hq + h))*Sq + s)*HDq + d;
                } else {
                    dst = C + (size_t)row * Eq + col;
                }
                *(float2*)dst = make_float2(v0, v1);
            }
        }
    }
}

// ===========================================================================
// tf32 mma.sync flash attention (unchanged from R5 — 152us, known good)
// ===========================================================================
#define KS_STR 68
#define VS_STR 72
#define PS_STR 68
#define ATTN_SMEM ((64*KS_STR + 64*VS_STR + 8*16*PS_STR) * 4)   // 70656

__global__ void __launch_bounds__(256, 2)
attn_mma(const float* __restrict__ Qg, const float* __restrict__ Kg,
         const float* __restrict__ Vg, float* __restrict__ ctx)
{
    extern __shared__ float smp[];
    float* Ks = smp;
    float* Vs = Ks + 64*KS_STR;
    float* Ps = Vs + 64*VS_STR;
    uint32_t* KsU = (uint32_t*)Ks;
    uint32_t* VsU = (uint32_t*)Vs;
    uint32_t* PsU = (uint32_t*)Ps;

    const int tid  = threadIdx.x;
    const int w    = tid >> 5;
    const int lane = tid & 31;
    const int g    = lane >> 2;
    const int tig  = lane & 3;
    const int qb = blockIdx.x, h = blockIdx.y, b = blockIdx.z;

    const float* Qp = Qg + (((size_t)(b*Hq + h))*Sq + qb*128) * HDq;
    const float* Kp = Kg + ((size_t)(b*Hq + h))*Sq*HDq;
    const float* Vp = Vg + ((size_t)(b*Hq + h))*Sq*HDq;

    {
        const float4* Q4 = (const float4*)Qp;
#pragma unroll
        for (int i = 0; i < 8; ++i) {
            int idx = tid + i*256;
            int r = idx >> 4, c4 = (idx & 15) * 4;
            float4 v = Q4[idx];
            uint32_t* d = PsU + r*PS_STR + c4;
            d[0] = f2tf32(v.x); d[1] = f2tf32(v.y);
            d[2] = f2tf32(v.z); d[3] = f2tf32(v.w);
        }
    }
    __syncthreads();

    uint32_t qf[8][4];
    {
        const uint32_t* q0 = PsU + (w*16 + g    )*PS_STR;
        const uint32_t* q1 = PsU + (w*16 + g + 8)*PS_STR;
#pragma unroll
        for (int ks = 0; ks < 8; ++ks) {
            qf[ks][0] = q0[ks*8 + tig];
            qf[ks][1] = q1[ks*8 + tig];
            qf[ks][2] = q0[ks*8 + tig + 4];
            qf[ks][3] = q1[ks*8 + tig + 4];
        }
    }
    __syncthreads();

    float acc[8][4];
#pragma unroll
    for (int n = 0; n < 8; ++n)
#pragma unroll
        for (int r = 0; r < 4; ++r) acc[n][r] = 0.f;
    float m0 = -1e30f, m1 = -1e30f, l0 = 0.f, l1 = 0.f;

    uint32_t* Pw = PsU + w*16*PS_STR;

    for (int kt = 0; kt < 16; ++kt) {
        __syncthreads();
        {
            const float4* Kt = (const float4*)(Kp + (size_t)kt*64*64);
            const float4* Vt = (const float4*)(Vp + (size_t)kt*64*64);
#pragma unroll
            for (int i = 0; i < 4; ++i) {
                int idx = tid + i*256;
                int r = idx >> 4, c4 = (idx & 15) * 4;
                float4 kv = Kt[idx];
                uint32_t* kd = KsU + r*KS_STR + c4;
                kd[0] = f2tf32(kv.x); kd[1] = f2tf32(kv.y);
                kd[2] = f2tf32(kv.z); kd[3] = f2tf32(kv.w);
                float4 vv = Vt[idx];
                uint32_t* vd = VsU + r*VS_STR + c4;
                vd[0] = f2tf32(vv.x); vd[1] = f2tf32(vv.y);
                vd[2] = f2tf32(vv.z); vd[3] = f2tf32(vv.w);
            }
        }
        __syncthreads();

        float sc[8][4];
#pragma unroll
        for (int n = 0; n < 8; ++n) {
#pragma unroll
            for (int r = 0; r < 4; ++r) sc[n][r] = 0.f;
            const uint32_t* kr = KsU + (n*8 + g)*KS_STR;
#pragma unroll
            for (int ks = 0; ks < 8; ++ks) {
                uint32_t bf[2] = { kr[ks*8 + tig], kr[ks*8 + tig + 4] };
                mma_tf32(sc[n], qf[ks], bf);
            }
        }

        {
            float mx0 = -1e30f, mx1 = -1e30f;
#pragma unroll
            for (int n = 0; n < 8; ++n) {
                mx0 = fmaxf(mx0, fmaxf(sc[n][0], sc[n][1]));
                mx1 = fmaxf(mx1, fmaxf(sc[n][2], sc[n][3]));
            }
            mx0 = fmaxf(mx0, __shfl_xor_sync(0xffffffffu, mx0, 1));
            mx0 = fmaxf(mx0, __shfl_xor_sync(0xffffffffu, mx0, 2));
            mx1 = fmaxf(mx1, __shfl_xor_sync(0xffffffffu, mx1, 1));
            mx1 = fmaxf(mx1, __shfl_xor_sync(0xffffffffu, mx1, 2));
            float mn0 = fmaxf(m0, mx0), mn1 = fmaxf(m1, mx1);
            float a0 = __expf(m0 - mn0), a1 = __expf(m1 - mn1);
            m0 = mn0; m1 = mn1;
            float rs0 = 0.f, rs1 = 0.f;
#pragma unroll
            for (int n = 0; n < 8; ++n) {
                sc[n][0] = __expf(sc[n][0] - mn0);
                sc[n][1] = __expf(sc[n][1] - mn0);
                sc[n][2] = __expf(sc[n][2] - mn1);
                sc[n][3] = __expf(sc[n][3] - mn1);
                rs0 += sc[n][0] + sc[n][1];
                rs1 += sc[n][2] + sc[n][3];
            }
            rs0 += __shfl_xor_sync(0xffffffffu, rs0, 1);
            rs0 += __shfl_xor_sync(0xffffffffu, rs0, 2);
            rs1 += __shfl_xor_sync(0xffffffffu, rs1, 1);
            rs1 += __shfl_xor_sync(0xffffffffu, rs1, 2);
            l0 = l0*a0 + rs0;
            l1 = l1*a1 + rs1;
#pragma unroll
            for (int n = 0; n < 8; ++n) {
                acc[n][0] *= a0; acc[n][1] *= a0;
                acc[n][2] *= a1; acc[n][3] *= a1;
            }
        }

#pragma unroll
        for (int n = 0; n < 8; ++n) {
            uint32_t* p0 = Pw + g*PS_STR + n*8 + 2*tig;
            uint32_t* p1 = Pw + (g+8)*PS_STR + n*8 + 2*tig;
            p0[0] = f2tf32(sc[n][0]); p0[1] = f2tf32(sc[n][1]);
            p1[0] = f2tf32(sc[n][2]); p1[1] = f2tf32(sc[n][3]);
        }
        __syncwarp();

        uint32_t af[8][4];
#pragma unroll
        for (int ks = 0; ks < 8; ++ks) {
            af[ks][0] = Pw[ g   *PS_STR + ks*8 + tig];
            af[ks][1] = Pw[(g+8)*PS_STR + ks*8 + tig];
            af[ks][2] = Pw[ g   *PS_STR + ks*8 + tig + 4];
            af[ks][3] = Pw[(g+8)*PS_STR + ks*8 + tig + 4];
        }
#pragma unroll
        for (int n = 0; n < 8; ++n) {
#pragma unroll
            for (int ks = 0; ks < 8; ++ks) {
                uint32_t bf[2] = { VsU[(ks*8 + tig  )*VS_STR + n*8 + g],
                                   VsU[(ks*8 + tig+4)*VS_STR + n*8 + g] };
                mma_tf32(acc[n], af[ks], bf);
            }
        }
    }

    float inv0 = 1.0f / l0, inv1 = 1.0f / l1;
    int row0 = qb*128 + w*16 + g;
#pragma unroll
    for (int n = 0; n < 8; ++n) {
        int e = h*64 + n*8 + 2*tig;
        float* d0 = ctx + ((size_t)b*Sq + row0    )*Eq + e;
        float* d1 = ctx + ((size_t)b*Sq + row0 + 8)*Eq + e;
        *(float2*)d0 = make_float2(acc[n][0]*inv0, acc[n][1]*inv0);
        *(float2*)d1 = make_float2(acc[n][2]*inv1, acc[n][3]*inv1);
    }
}

// ---------------------------------------------------------------------------
extern "C" void kernel_launch(void* const* d_in, const int* in_sizes, int n_in,
                              void* d_out, int out_size)
{
    const float* q  = (const float*)d_in[0];
    const float* k  = (const float*)d_in[1];
    const float* v  = (const float*)d_in[2];
    const float* Wq = (const float*)d_in[3];
    const float* Wk = (const float*)d_in[4];
    const float* Wv = (const float*)d_in[5];
    const float* Wo = (const float*)d_in[6];
    float* out = (float*)d_out;

    float *gQ, *gK, *gV, *gctx;
    cudaGetSymbolAddress((void**)&gQ,   g_Q);
    cudaGetSymbolAddress((void**)&gK,   g_K);
    cudaGetSymbolAddress((void**)&gV,   g_V);
    cudaGetSymbolAddress((void**)&gctx, g_ctx);

    cudaFuncSetAttribute(gemm_mma, cudaFuncAttributeMaxDynamicSharedMemorySize,
                         GEMM_SMEM);
    cudaFuncSetAttribute(attn_mma, cudaFuncAttributeMaxDynamicSharedMemorySize,
                         ATTN_SMEM);

    dim3 ggrid(Eq/128, Mtot/128);   // (8, 32) = 256 CTAs

    gemm_mma<<<ggrid, 256, GEMM_SMEM>>>(q, Wq, gQ, 1, 0.125f);
    gemm_mma<<<ggrid, 256, GEMM_SMEM>>>(k, Wk, gK, 1, 1.0f);
    gemm_mma<<<ggrid, 256, GEMM_SMEM>>>(v, Wv, gV, 1, 1.0f);

    attn_mma<<<dim3(Sq/128, Hq, Bq), 256, ATTN_SMEM>>>(gQ, gK, gV, gctx);

    gemm_mma<<<ggrid, 256, GEMM_SMEM>>>(gctx, Wo, out, 0, 1.0f);
}

// round 7
// speedup vs baseline: 3.5991x; 1.0046x over previous
#include <cuda_runtime.h>
#include <cstdint>

#define Bq 4
#define Sq 1024
#define Eq 1024
#define Hq 16
#define HDq 64
#define Mtot (Bq*Sq)   // 4096

// Scratch (static device globals: allocation-free)
__device__ float g_Q[Bq*Hq*Sq*HDq];    // [B,H,S,HD] (tf32-rounded)
__device__ float g_K[Bq*Hq*Sq*HDq];
__device__ float g_V[Bq*Hq*Sq*HDq];
__device__ float g_ctx[Bq*Sq*Eq];      // [B,S,E] (tf32-rounded)
__device__ float g_qc[Mtot*Eq];        // tf32-rounded inputs
__device__ float g_kc[Mtot*Eq];
__device__ float g_vc[Mtot*Eq];
__device__ float g_wc[4][Eq*Eq];       // tf32-rounded weights

__device__ __forceinline__ uint32_t f2tf32(float x) {
    uint32_t r;
    asm("cvt.rna.tf32.f32 %0, %1;" : "=r"(r) : "f"(x));
    return r;
}

__device__ __forceinline__ uint32_t smem_u32(const void* p) {
    uint32_t a;
    asm("{ .reg .u64 t; cvta.to.shared.u64 t, %1; cvt.u32.u64 %0, t; }"
        : "=r"(a) : "l"(p));
    return a;
}

__device__ __forceinline__ void cp_async16(uint32_t dst, const void* src) {
    asm volatile("cp.async.cg.shared.global [%0], [%1], 16;"
                 :: "r"(dst), "l"(src));
}
#define CP_COMMIT()  asm volatile("cp.async.commit_group;" ::: "memory")
#define CP_WAIT2()   asm volatile("cp.async.wait_group 2;" ::: "memory")
#define CP_WAIT1()   asm volatile("cp.async.wait_group 1;" ::: "memory")

__device__ __forceinline__ void mma_tf32(float c[4], const uint32_t a[4],
                                         const uint32_t b[2]) {
    asm volatile(
        "mma.sync.aligned.m16n8k8.row.col.f32.tf32.tf32.f32 "
        "{%0,%1,%2,%3}, {%4,%5,%6,%7}, {%8,%9}, {%0,%1,%2,%3};"
        : "+f"(c[0]), "+f"(c[1]), "+f"(c[2]), "+f"(c[3])
        : "r"(a[0]), "r"(a[1]), "r"(a[2]), "r"(a[3]), "r"(b[0]), "r"(b[1]));
}

// ===========================================================================
// RNA fp32 -> tf32 pre-conversion pass (elementwise, memory-bound)
// ===========================================================================
__global__ void __launch_bounds__(256)
cvt_tf32(const float4* __restrict__ src, float4* __restrict__ dst)
{
    int i = blockIdx.x * 256 + threadIdx.x;
    float4 v = src[i];
    dst[i] = make_float4(__uint_as_float(f2tf32(v.x)),
                         __uint_as_float(f2tf32(v.y)),
                         __uint_as_float(f2tf32(v.z)),
                         __uint_as_float(f2tf32(v.w)));
}

// ===========================================================================
// tf32 mma.sync NT GEMM, inputs pre-converted to tf32 (no cvt in loop).
// C[M,N] = A[M,K] @ W[N,K]^T, K = 1024. Block 128x128, 4 warps (2m x 2n),
// warp tile 64x64. cp.async 4-stage pipeline, smem [row][k16] stride 20
// (fragment LDS conflict-free: g*20+tig distinct mod 32).
// remap=1: scatter into [B,H,S,HD], values tf32-rounded; remap=0: row-major
// plain fp32. scale applied in epilogue before rounding.
// ===========================================================================
#define RSTR 20
#define STAGE_FLOATS (128*RSTR)            // 2560 floats per operand-stage
#define GEMM_SMEM (8*STAGE_FLOATS*4)       // 4 stages x (A,W) = 81920 B
#define NSTAGE 64                          // 1024 / 16

__global__ void __launch_bounds__(128, 2)
gemm_mma(const float* __restrict__ A, const float* __restrict__ W,
         float* __restrict__ C, int remap, float scale)
{
    extern __shared__ float sm[];
    const uint32_t smb = smem_u32(sm);

    const int tid  = threadIdx.x;
    const int wid  = tid >> 5;
    const int lane = tid & 31;
    const int g    = lane >> 2;
    const int tig  = lane & 3;
    const int wm   = (wid & 1) * 64;
    const int wn   = (wid >> 1) * 64;
    const int m0 = blockIdx.y * 128;
    const int n0 = blockIdx.x * 128;

    // cp.async mapping: idx = tid + i*128, i=0..3 -> row = (tid>>2)+32i,
    // kc = (tid&3)*4 (same for all i)
    const int r0 = tid >> 2;
    const int kc = (tid & 3) * 4;

    const float* Ag = A + (size_t)(m0 + r0) * Eq + kc;
    const float* Wg = W + (size_t)(n0 + r0) * Eq + kc;
    const uint32_t sa = smb + (r0*RSTR + kc) * 4;
    const uint32_t sw = sa + STAGE_FLOATS * 4;

    float c[4][8][4];
#pragma unroll
    for (int mt = 0; mt < 4; ++mt)
#pragma unroll
        for (int nt = 0; nt < 8; ++nt)
#pragma unroll
            for (int r = 0; r < 4; ++r) c[mt][nt][r] = 0.f;

    // prologue: stages 0..2
#pragma unroll
    for (int p = 0; p < 3; ++p) {
        uint32_t so = (uint32_t)(p * 2 * STAGE_FLOATS * 4);
        int k0 = p * 16;
#pragma unroll
        for (int i = 0; i < 4; ++i) {
            cp_async16(sa + so + i*32*RSTR*4, Ag + k0 + (size_t)i*32*Eq);
            cp_async16(sw + so + i*32*RSTR*4, Wg + k0 + (size_t)i*32*Eq);
        }
        CP_COMMIT();
    }

    for (int s = 0; s < NSTAGE; ++s) {
        CP_WAIT2();          // stage s resident
        __syncthreads();     // stage s visible; reads of stage s-1 retired

        if (s + 3 < NSTAGE) {
            uint32_t so = (uint32_t)(((s + 3) & 3) * 2 * STAGE_FLOATS * 4);
            int k0 = (s + 3) * 16;
#pragma unroll
            for (int i = 0; i < 4; ++i) {
                cp_async16(sa + so + i*32*RSTR*4, Ag + k0 + (size_t)i*32*Eq);
                cp_async16(sw + so + i*32*RSTR*4, Wg + k0 + (size_t)i*32*Eq);
            }
        }
        CP_COMMIT();         // always commit: 3 groups pending at loop top

        const float* Ab = sm + (s & 3) * 2 * STAGE_FLOATS;
        const float* Wb = Ab + STAGE_FLOATS;

#pragma unroll
        for (int ks = 0; ks < 16; ks += 8) {
            uint32_t af[4][4], bf[8][2];
#pragma unroll
            for (int mt = 0; mt < 4; ++mt) {
                const float* a0 = Ab + (wm + mt*16 + g) * RSTR + ks;
                const float* a1 = a0 + 8 * RSTR;
                af[mt][0] = __float_as_uint(a0[tig]);
                af[mt][1] = __float_as_uint(a1[tig]);
                af[mt][2] = __float_as_uint(a0[tig + 4]);
                af[mt][3] = __float_as_uint(a1[tig + 4]);
            }
#pragma unroll
            for (int nt = 0; nt < 8; ++nt) {
                const float* b0 = Wb + (wn + nt*8 + g) * RSTR + ks;
                bf[nt][0] = __float_as_uint(b0[tig]);
                bf[nt][1] = __float_as_uint(b0[tig + 4]);
            }
#pragma unroll
            for (int mt = 0; mt < 4; ++mt)
#pragma unroll
                for (int nt = 0; nt < 8; ++nt)
                    mma_tf32(c[mt][nt], af[mt], bf[nt]);
        }
    }

    // Epilogue
#pragma unroll
    for (int mt = 0; mt < 4; ++mt) {
#pragma unroll
        for (int nt = 0; nt < 8; ++nt) {
            int row0 = m0 + wm + mt*16 + g;
            int col  = n0 + wn + nt*8 + 2*tig;
#pragma unroll
            for (int half = 0; half < 2; ++half) {
                int row = row0 + half*8;
                float v0 = c[mt][nt][half*2+0] * scale;
                float v1 = c[mt][nt][half*2+1] * scale;
                if (remap) {
                    int b = row >> 10, s = row & 1023;
                    int h = col >> 6, d = col & 63;
                    float* dst = C + (((size_t)(b*Hq + h))*Sq + s)*HDq + d;
                    *(float2*)dst = make_float2(__uint_as_float(f2tf32(v0)),
                                                __uint_as_float(f2tf32(v1)));
                } else {
                    float* dst = C + (size_t)row * Eq + col;
                    *(float2*)dst = make_float2(v0, v1);
                }
            }
        }
    }
}

// ===========================================================================
// tf32 mma.sync flash attention. Q/K/V pre-rounded to tf32 (no cvt on load).
// K/V staged via double-buffered cp.async (prefetch kt+1 during kt compute).
// Block = 128 q rows x (head, batch); 8 warps x 16 q rows.
// smem: [Ks0|Vs0][Ks1|Vs1][Ps], strides 68/72/68.
// ===========================================================================
#define KS_STR 68
#define VS_STR 72
#define PS_STR 68
#define BUF_FLOATS (64*KS_STR + 64*VS_STR)             // 8960
#define ATTN_SMEM ((2*BUF_FLOATS + 8*16*PS_STR) * 4)   // 106496

__global__ void __launch_bounds__(256, 2)
attn_mma(const float* __restrict__ Qg, const float* __restrict__ Kg,
         const float* __restrict__ Vg, float* __restrict__ ctx)
{
    extern __shared__ float smp[];
    float* Ps = smp + 2*BUF_FLOATS;
    uint32_t* PsU = (uint32_t*)Ps;
    const uint32_t smb = smem_u32(smp);

    const int tid  = threadIdx.x;
    const int w    = tid >> 5;
    const int lane = tid & 31;
    const int g    = lane >> 2;
    const int tig  = lane & 3;
    const int qb = blockIdx.x, h = blockIdx.y, b = blockIdx.z;

    const float* Qp = Qg + (((size_t)(b*Hq + h))*Sq + qb*128) * HDq;
    const float* Kp = Kg + ((size_t)(b*Hq + h))*Sq*HDq;
    const float* Vp = Vg + ((size_t)(b*Hq + h))*Sq*HDq;

    // cp.async staging indices for K/V tiles (64x64)
    const int sr  = tid >> 2;            // base row lane mapping for idx=tid
    const int sc4 = (tid & 3) * 4;

    // issue K/V tile kt into buffer kt&1
    auto issue_tile = [&](int kt) {
        const float4* Kt = (const float4*)(Kp + (size_t)kt*64*64);
        const float4* Vt = (const float4*)(Vp + (size_t)kt*64*64);
        uint32_t kb = smb + (uint32_t)((kt & 1) * BUF_FLOATS * 4);
        uint32_t vb = kb + 64*KS_STR*4;
#pragma unroll
        for (int i = 0; i < 4; ++i) {
            int idx = tid + i*256;
            int r = idx >> 4, c4 = (idx & 15) * 4;
            cp_async16(kb + (uint32_t)((r*KS_STR + c4)*4), Kt + idx);
            cp_async16(vb + (uint32_t)((r*VS_STR + c4)*4), Vt + idx);
        }
    };

    // start tile 0 immediately (overlaps Q staging)
    issue_tile(0);
    CP_COMMIT();

    // ---- Stage Q (already tf32 bits) into Ps region [128][68] ----
    {
        const float4* Q4 = (const float4*)Qp;
#pragma unroll
        for (int i = 0; i < 8; ++i) {
            int idx = tid + i*256;
            int r = idx >> 4, c4 = (idx & 15) * 4;
            *(float4*)(Ps + r*PS_STR + c4) = Q4[idx];
        }
    }
    __syncthreads();

    uint32_t qf[8][4];
    {
        const uint32_t* q0 = PsU + (w*16 + g    )*PS_STR;
        const uint32_t* q1 = PsU + (w*16 + g + 8)*PS_STR;
#pragma unroll
        for (int ks = 0; ks < 8; ++ks) {
            qf[ks][0] = q0[ks*8 + tig];
            qf[ks][1] = q1[ks*8 + tig];
            qf[ks][2] = q0[ks*8 + tig + 4];
            qf[ks][3] = q1[ks*8 + tig + 4];
        }
    }

    float acc[8][4];
#pragma unroll
    for (int n = 0; n < 8; ++n)
#pragma unroll
        for (int r = 0; r < 4; ++r) acc[n][r] = 0.f;
    float m0 = -1e30f, m1 = -1e30f, l0 = 0.f, l1 = 0.f;

    uint32_t* Pw = PsU + w*16*PS_STR;

    for (int kt = 0; kt < 16; ++kt) {
        __syncthreads();   // all reads of buffer (kt+1)&1 (tile kt-1) + Ps done
        if (kt + 1 < 16) issue_tile(kt + 1);
        CP_COMMIT();
        CP_WAIT1();        // tile kt resident; kt+1 in flight
        __syncthreads();

        const uint32_t* KsU = (const uint32_t*)(smp + (kt & 1) * BUF_FLOATS);
        const uint32_t* VsU = KsU + 64*KS_STR;

        // ---- S = Q @ K^T ----
        float sc[8][4];
#pragma unroll
        for (int n = 0; n < 8; ++n) {
#pragma unroll
            for (int r = 0; r < 4; ++r) sc[n][r] = 0.f;
            const uint32_t* kr = KsU + (n*8 + g)*KS_STR;
#pragma unroll
            for (int ks = 0; ks < 8; ++ks) {
                uint32_t bf[2] = { kr[ks*8 + tig], kr[ks*8 + tig + 4] };
                mma_tf32(sc[n], qf[ks], bf);
            }
        }

        // ---- online softmax ----
        {
            float mx0 = -1e30f, mx1 = -1e30f;
#pragma unroll
            for (int n = 0; n < 8; ++n) {
                mx0 = fmaxf(mx0, fmaxf(sc[n][0], sc[n][1]));
                mx1 = fmaxf(mx1, fmaxf(sc[n][2], sc[n][3]));
            }
            mx0 = fmaxf(mx0, __shfl_xor_sync(0xffffffffu, mx0, 1));
            mx0 = fmaxf(mx0, __shfl_xor_sync(0xffffffffu, mx0, 2));
            mx1 = fmaxf(mx1, __shfl_xor_sync(0xffffffffu, mx1, 1));
            mx1 = fmaxf(mx1, __shfl_xor_sync(0xffffffffu, mx1, 2));
            float mn0 = fmaxf(m0, mx0), mn1 = fmaxf(m1, mx1);
            float a0 = __expf(m0 - mn0), a1 = __expf(m1 - mn1);
            m0 = mn0; m1 = mn1;
            float rs0 = 0.f, rs1 = 0.f;
#pragma unroll
            for (int n = 0; n < 8; ++n) {
                sc[n][0] = __expf(sc[n][0] - mn0);
                sc[n][1] = __expf(sc[n][1] - mn0);
                sc[n][2] = __expf(sc[n][2] - mn1);
                sc[n][3] = __expf(sc[n][3] - mn1);
                rs0 += sc[n][0] + sc[n][1];
                rs1 += sc[n][2] + sc[n][3];
            }
            rs0 += __shfl_xor_sync(0xffffffffu, rs0, 1);
            rs0 += __shfl_xor_sync(0xffffffffu, rs0, 2);
            rs1 += __shfl_xor_sync(0xffffffffu, rs1, 1);
            rs1 += __shfl_xor_sync(0xffffffffu, rs1, 2);
            l0 = l0*a0 + rs0;
            l1 = l1*a1 + rs1;
#pragma unroll
            for (int n = 0; n < 8; ++n) {
                acc[n][0] *= a0; acc[n][1] *= a0;
                acc[n][2] *= a1; acc[n][3] *= a1;
            }
        }

        // ---- P (tf32) -> per-warp smem ----
#pragma unroll
        for (int n = 0; n < 8; ++n) {
            uint32_t* p0 = Pw + g*PS_STR + n*8 + 2*tig;
            uint32_t* p1 = Pw + (g+8)*PS_STR + n*8 + 2*tig;
            p0[0] = f2tf32(sc[n][0]); p0[1] = f2tf32(sc[n][1]);
            p1[0] = f2tf32(sc[n][2]); p1[1] = f2tf32(sc[n][3]);
        }
        __syncwarp();

        // ---- O += P @ V ----
        uint32_t af[8][4];
#pragma unroll
        for (int ks = 0; ks < 8; ++ks) {
            af[ks][0] = Pw[ g   *PS_STR + ks*8 + tig];
            af[ks][1] = Pw[(g+8)*PS_STR + ks*8 + tig];
            af[ks][2] = Pw[ g   *PS_STR + ks*8 + tig + 4];
            af[ks][3] = Pw[(g+8)*PS_STR + ks*8 + tig + 4];
        }
#pragma unroll
        for (int n = 0; n < 8; ++n) {
#pragma unroll
            for (int ks = 0; ks < 8; ++ks) {
                uint32_t bf[2] = { VsU[(ks*8 + tig  )*VS_STR + n*8 + g],
                                   VsU[(ks*8 + tig+4)*VS_STR + n*8 + g] };
                mma_tf32(acc[n], af[ks], bf);
            }
        }
    }

    // ---- normalize, round to tf32, write ctx [B,S,E] ----
    float inv0 = 1.0f / l0, inv1 = 1.0f / l1;
    int row0 = qb*128 + w*16 + g;
#pragma unroll
    for (int n = 0; n < 8; ++n) {
        int e = h*64 + n*8 + 2*tig;
        float* d0 = ctx + ((size_t)b*Sq + row0    )*Eq + e;
        float* d1 = ctx + ((size_t)b*Sq + row0 + 8)*Eq + e;
        *(float2*)d0 = make_float2(__uint_as_float(f2tf32(acc[n][0]*inv0)),
                                   __uint_as_float(f2tf32(acc[n][1]*inv0)));
        *(float2*)d1 = make_float2(__uint_as_float(f2tf32(acc[n][2]*inv1)),
                                   __uint_as_float(f2tf32(acc[n][3]*inv1)));
    }
}

// ---------------------------------------------------------------------------
extern "C" void kernel_launch(void* const* d_in, const int* in_sizes, int n_in,
                              void* d_out, int out_size)
{
    const float* q  = (const float*)d_in[0];
    const float* k  = (const float*)d_in[1];
    const float* v  = (const float*)d_in[2];
    const float* Wq = (const float*)d_in[3];
    const float* Wk = (const float*)d_in[4];
    const float* Wv = (const float*)d_in[5];
    const float* Wo = (const float*)d_in[6];
    float* out = (float*)d_out;

    float *gQ, *gK, *gV, *gctx, *gqc, *gkc, *gvc, *gwc;
    cudaGetSymbolAddress((void**)&gQ,   g_Q);
    cudaGetSymbolAddress((void**)&gK,   g_K);
    cudaGetSymbolAddress((void**)&gV,   g_V);
    cudaGetSymbolAddress((void**)&gctx, g_ctx);
    cudaGetSymbolAddress((void**)&gqc,  g_qc);
    cudaGetSymbolAddress((void**)&gkc,  g_kc);
    cudaGetSymbolAddress((void**)&gvc,  g_vc);
    cudaGetSymbolAddress((void**)&gwc,  g_wc);

    cudaFuncSetAttribute(gemm_mma, cudaFuncAttributeMaxDynamicSharedMemorySize,
                         GEMM_SMEM);
    cudaFuncSetAttribute(attn_mma, cudaFuncAttributeMaxDynamicSharedMemorySize,
                         ATTN_SMEM);

    // Pre-convert inputs + weights to tf32 (RNA)
    const int NB_IN = (Mtot*Eq/4) / 256;   // 4096 blocks
    const int NB_W  = (Eq*Eq/4) / 256;     // 1024 blocks
    cvt_tf32<<<NB_IN, 256>>>((const float4*)q, (float4*)gqc);
    cvt_tf32<<<NB_IN, 256>>>((const float4*)k, (float4*)gkc);
    cvt_tf32<<<NB_IN, 256>>>((const float4*)v, (float4*)gvc);
    cvt_tf32<<<NB_W, 256>>>((const float4*)Wq, (float4*)(gwc + 0*Eq*Eq));
    cvt_tf32<<<NB_W, 256>>>((const float4*)Wk, (float4*)(gwc + 1*Eq*Eq));
    cvt_tf32<<<NB_W, 256>>>((const float4*)Wv, (float4*)(gwc + 2*Eq*Eq));
    cvt_tf32<<<NB_W, 256>>>((const float4*)Wo, (float4*)(gwc + 3*Eq*Eq));

    dim3 ggrid(Eq/128, Mtot/128);   // (8, 32) = 256 CTAs, occ 2

    // Projections (softmax scale folded into Q epilogue, outputs tf32-rounded)
    gemm_mma<<<ggrid, 128, GEMM_SMEM>>>(gqc, gwc + 0*Eq*Eq, gQ, 1, 0.125f);
    gemm_mma<<<ggrid, 128, GEMM_SMEM>>>(gkc, gwc + 1*Eq*Eq, gK, 1, 1.0f);
    gemm_mma<<<ggrid, 128, GEMM_SMEM>>>(gvc, gwc + 2*Eq*Eq, gV, 1, 1.0f);

    attn_mma<<<dim3(Sq/128, Hq, Bq), 256, ATTN_SMEM>>>(gQ, gK, gV, gctx);

    // Output projection straight into d_out (plain fp32)
    gemm_mma<<<ggrid, 128, GEMM_SMEM>>>(gctx, gwc + 3*Eq*Eq, out, 0, 1.0f);
}

// round 8
// speedup vs baseline: 6.0514x; 1.6814x over previous
#include <cuda_runtime.h>
#include <cuda_fp16.h>
#include <cstdint>

#define Bq 4
#define Sq 1024
#define Eq 1024
#define Hq 16
#define HDq 64
#define Mtot (Bq*Sq)   // 4096

// Scratch (static device globals: allocation-free). fp16 stored as uint16_t.
__device__ uint16_t g_Q[Bq*Hq*Sq*HDq];    // [B,H,S,HD] fp16
__device__ uint16_t g_K[Bq*Hq*Sq*HDq];    // [B,H,S,HD] fp16
__device__ uint16_t g_VT[Bq*Hq*HDq*Sq];   // [B,H,HD,S] fp16 (transposed V)
__device__ uint16_t g_ctx[Bq*Sq*Eq];      // [B,S,E] fp16
__device__ uint16_t g_qc[Mtot*Eq];        // fp16-rounded inputs
__device__ uint16_t g_kc[Mtot*Eq];
__device__ uint16_t g_vc[Mtot*Eq];
__device__ uint16_t g_wc[4][Eq*Eq];       // fp16-rounded weights

__device__ __forceinline__ uint32_t smem_u32(const void* p) {
    uint32_t a;
    asm("{ .reg .u64 t; cvta.to.shared.u64 t, %1; cvt.u32.u64 %0, t; }"
        : "=r"(a) : "l"(p));
    return a;
}

__device__ __forceinline__ void cp_async16(uint32_t dst, const void* src) {
    asm volatile("cp.async.cg.shared.global [%0], [%1], 16;"
                 :: "r"(dst), "l"(src));
}
#define CP_COMMIT()  asm volatile("cp.async.commit_group;" ::: "memory")
#define CP_WAIT2()   asm volatile("cp.async.wait_group 2;" ::: "memory")
#define CP_WAIT1()   asm volatile("cp.async.wait_group 1;" ::: "memory")

__device__ __forceinline__ void mma_f16(float c[4], const uint32_t a[4],
                                        const uint32_t b[2]) {
    asm volatile(
        "mma.sync.aligned.m16n8k16.row.col.f32.f16.f16.f32 "
        "{%0,%1,%2,%3}, {%4,%5,%6,%7}, {%8,%9}, {%0,%1,%2,%3};"
        : "+f"(c[0]), "+f"(c[1]), "+f"(c[2]), "+f"(c[3])
        : "r"(a[0]), "r"(a[1]), "r"(a[2]), "r"(a[3]), "r"(b[0]), "r"(b[1]));
}

__device__ __forceinline__ uint32_t pack_h2(float x, float y) {
    __half2 h = __floats2half2_rn(x, y);
    return *(uint32_t*)&h;
}

// ===========================================================================
// fp32 -> fp16 (RN) pre-conversion pass (memory-bound)
// ===========================================================================
__global__ void __launch_bounds__(256)
cvt_f16(const float4* __restrict__ src, uint2* __restrict__ dst)
{
    int i = blockIdx.x * 256 + threadIdx.x;
    float4 v = src[i];
    dst[i] = make_uint2(pack_h2(v.x, v.y), pack_h2(v.z, v.w));
}

// ===========================================================================
// fp16 mma.sync NT GEMM: C[M,N] = A[M,K] @ W[N,K]^T, K = 1024, fp32 accum.
// Block 128x128, 8 warps (2m x 4n), warp tile 64x32. cp.async 4-stage ring,
// stage = 32 halves of K per row, smem row stride 20 words (16 used + 4 pad,
// conflict-free: g*20+tig distinct mod 32).
// remap=0: fp32 row-major out; remap=1: fp16 [B,H,S,HD]; remap=2: fp16
// transposed [B,H,HD,S]. scale applied before rounding.
// ===========================================================================
#define RSTRW 20
#define STAGE_W (128*RSTRW)                // 2560 words per operand-stage
#define GEMM_SMEM (8*STAGE_W*4)            // 4 stages x (A,W) = 81920 B
#define NSTG 32                            // 1024 / 32

__global__ void __launch_bounds__(256, 2)
gemm_h(const uint16_t* __restrict__ A, const uint16_t* __restrict__ W,
       void* __restrict__ Cv, int remap, float scale)
{
    extern __shared__ uint32_t smw[];
    const uint32_t smb = smem_u32(smw);

    const int tid  = threadIdx.x;
    const int wid  = tid >> 5;
    const int lane = tid & 31;
    const int g    = lane >> 2;
    const int tig  = lane & 3;
    const int wm   = (wid & 1) * 64;
    const int wn   = (wid >> 1) * 32;
    const int m0 = blockIdx.y * 128;
    const int n0 = blockIdx.x * 128;

    // staging: idx = tid + i*256 (i=0,1): row = idx>>2, 8-half chunk (tid&3)
    const int r0  = tid >> 2;              // 0..63 (+64 for i=1)
    const int kc8 = (tid & 3) * 8;         // half offset within 32-half stage

    const uint16_t* Ag = A + (size_t)(m0 + r0) * Eq + kc8;
    const uint16_t* Wg = W + (size_t)(n0 + r0) * Eq + kc8;
    const uint32_t sa = smb + (uint32_t)(r0*RSTRW + (tid & 3)*4) * 4;
    const uint32_t sw = sa + STAGE_W * 4;

    float c[4][4][4];
#pragma unroll
    for (int mt = 0; mt < 4; ++mt)
#pragma unroll
        for (int nt = 0; nt < 4; ++nt)
#pragma unroll
            for (int r = 0; r < 4; ++r) c[mt][nt][r] = 0.f;

    // prologue: stages 0..2
#pragma unroll
    for (int p = 0; p < 3; ++p) {
        uint32_t so = (uint32_t)(p * 2 * STAGE_W * 4);
        int k0 = p * 32;
#pragma unroll
        for (int i = 0; i < 2; ++i) {
            cp_async16(sa + so + i*64*RSTRW*4, Ag + k0 + (size_t)i*64*Eq);
            cp_async16(sw + so + i*64*RSTRW*4, Wg + k0 + (size_t)i*64*Eq);
        }
        CP_COMMIT();
    }

    for (int s = 0; s < NSTG; ++s) {
        CP_WAIT2();
        __syncthreads();

        if (s + 3 < NSTG) {
            uint32_t so = (uint32_t)(((s + 3) & 3) * 2 * STAGE_W * 4);
            int k0 = (s + 3) * 32;
#pragma unroll
            for (int i = 0; i < 2; ++i) {
                cp_async16(sa + so + i*64*RSTRW*4, Ag + k0 + (size_t)i*64*Eq);
                cp_async16(sw + so + i*64*RSTRW*4, Wg + k0 + (size_t)i*64*Eq);
            }
        }
        CP_COMMIT();

        const uint32_t* Ab = smw + (s & 3) * 2 * STAGE_W;
        const uint32_t* Wb = Ab + STAGE_W;

#pragma unroll
        for (int s2 = 0; s2 < 2; ++s2) {   // two k16 slices per stage
            const int base = s2 * 8;
            uint32_t af[4][4], bf[4][2];
#pragma unroll
            for (int mt = 0; mt < 4; ++mt) {
                const uint32_t* a0 = Ab + (wm + mt*16 + g) * RSTRW + base;
                const uint32_t* a1 = a0 + 8 * RSTRW;
                af[mt][0] = a0[tig];
                af[mt][1] = a1[tig];
                af[mt][2] = a0[tig + 4];
                af[mt][3] = a1[tig + 4];
            }
#pragma unroll
            for (int nt = 0; nt < 4; ++nt) {
                const uint32_t* b0 = Wb + (wn + nt*8 + g) * RSTRW + base;
                bf[nt][0] = b0[tig];
                bf[nt][1] = b0[tig + 4];
            }
#pragma unroll
            for (int mt = 0; mt < 4; ++mt)
#pragma unroll
                for (int nt = 0; nt < 4; ++nt)
                    mma_f16(c[mt][nt], af[mt], bf[nt]);
        }
    }

    // Epilogue
#pragma unroll
    for (int mt = 0; mt < 4; ++mt) {
#pragma unroll
        for (int nt = 0; nt < 4; ++nt) {
            int row0 = m0 + wm + mt*16 + g;
            int col  = n0 + wn + nt*8 + 2*tig;
#pragma unroll
            for (int half = 0; half < 2; ++half) {
                int row = row0 + half*8;
                float v0 = c[mt][nt][half*2+0] * scale;
                float v1 = c[mt][nt][half*2+1] * scale;
                if (remap == 0) {
                    float* dst = (float*)Cv + (size_t)row * Eq + col;
                    *(float2*)dst = make_float2(v0, v1);
                } else if (remap == 1) {
                    int b = row >> 10, s = row & 1023;
                    int h = col >> 6, d = col & 63;
                    uint32_t* dst = (uint32_t*)((uint16_t*)Cv +
                        ((((size_t)(b*Hq + h))*Sq + s)*HDq + d));
                    *dst = pack_h2(v0, v1);
                } else {
                    // transposed: [B,H,HD,S]
                    int b = row >> 10, s = row & 1023;
                    int h = col >> 6, d = col & 63;
                    uint16_t* dst = (uint16_t*)Cv +
                        (((size_t)(b*Hq + h))*HDq + d)*Sq + s;
                    __half h0 = __float2half_rn(v0);
                    __half h1 = __float2half_rn(v1);
                    dst[0]  = *(uint16_t*)&h0;
                    dst[Sq] = *(uint16_t*)&h1;
                }
            }
        }
    }
}

// ===========================================================================
// fp16 mma.sync flash attention. Q/K fp16 [B,H,S,HD]; V fp16 transposed
// [B,H,HD,S]. Block = 128 q rows x (head, batch); 8 warps x 16 q rows.
// K/V double-buffered cp.async. P roundtrips per-warp smem as fp16.
// smem rows stride 36 words (32 used + 4 pad; g*36+tig ≡ g*4+tig mod 32).
// ===========================================================================
#define QSTRW 36
#define TILE_W (64*QSTRW)                  // 2304 words (one K or V tile)
#define BUF_W (2*TILE_W)                   // K+V per buffer
#define PQ_W (128*QSTRW)                   // Q staging / P region
#define ATTN_SMEM ((2*BUF_W + PQ_W)*4)     // 55296 B

__global__ void __launch_bounds__(256, 2)
attn_h(const uint16_t* __restrict__ Qg, const uint16_t* __restrict__ Kg,
       const uint16_t* __restrict__ VTg, uint16_t* __restrict__ ctx)
{
    extern __shared__ uint32_t smw[];
    uint32_t* Pq = smw + 2*BUF_W;
    const uint32_t smb = smem_u32(smw);

    const int tid  = threadIdx.x;
    const int w    = tid >> 5;
    const int lane = tid & 31;
    const int g    = lane >> 2;
    const int tig  = lane & 3;
    const int qb = blockIdx.x, h = blockIdx.y, b = blockIdx.z;

    const uint16_t* Qp  = Qg  + (((size_t)(b*Hq + h))*Sq + qb*128) * HDq;
    const uint16_t* Kp  = Kg  + ((size_t)(b*Hq + h))*Sq*HDq;
    const uint16_t* VTp = VTg + ((size_t)(b*Hq + h))*HDq*Sq;

    // issue K/V tile kt into buffer kt&1 (K: [kv][hd] rows; V: [hd][kv] rows)
    auto issue_tile = [&](int kt) {
        uint32_t kb = smb + (uint32_t)((kt & 1) * BUF_W * 4);
        uint32_t vb = kb + TILE_W * 4;
#pragma unroll
        for (int i = 0; i < 2; ++i) {
            int idx = tid + i*256;
            int r = idx >> 3, c8 = idx & 7;
            uint32_t so = (uint32_t)((r*QSTRW + c8*4) * 4);
            cp_async16(kb + so, Kp + (size_t)(kt*64 + r)*HDq + c8*8);
            cp_async16(vb + so, VTp + (size_t)r*Sq + kt*64 + c8*8);
        }
    };

    issue_tile(0);
    CP_COMMIT();

    // ---- Stage Q (fp16) into Pq region [128][36w] ----
    {
        const uint4* Q4 = (const uint4*)Qp;   // 1024 16B chunks
#pragma unroll
        for (int i = 0; i < 4; ++i) {
            int idx = tid + i*256;
            int r = idx >> 3, c8 = idx & 7;
            *(uint4*)(Pq + r*QSTRW + c8*4) = Q4[idx];
        }
    }
    __syncthreads();

    uint32_t qf[4][4];
    {
        const uint32_t* q0 = Pq + (w*16 + g    )*QSTRW;
        const uint32_t* q1 = Pq + (w*16 + g + 8)*QSTRW;
#pragma unroll
        for (int s = 0; s < 4; ++s) {
            qf[s][0] = q0[s*8 + tig];
            qf[s][1] = q1[s*8 + tig];
            qf[s][2] = q0[s*8 + tig + 4];
            qf[s][3] = q1[s*8 + tig + 4];
        }
    }

    float acc[8][4];
#pragma unroll
    for (int n = 0; n < 8; ++n)
#pragma unroll
        for (int r = 0; r < 4; ++r) acc[n][r] = 0.f;
    float m0 = -1e30f, m1 = -1e30f, l0 = 0.f, l1 = 0.f;

    uint32_t* Pw = Pq + w*16*QSTRW;

    for (int kt = 0; kt < 16; ++kt) {
        __syncthreads();   // prior buffer reads + P/Q region reads retired
        if (kt + 1 < 16) issue_tile(kt + 1);
        CP_COMMIT();
        CP_WAIT1();        // tile kt resident; kt+1 in flight
        __syncthreads();

        const uint32_t* KsW = smw + (kt & 1) * BUF_W;
        const uint32_t* VsW = KsW + TILE_W;

        // ---- S = Q @ K^T ----
        float sc[8][4];
#pragma unroll
        for (int n = 0; n < 8; ++n) {
#pragma unroll
            for (int r = 0; r < 4; ++r) sc[n][r] = 0.f;
            const uint32_t* kr = KsW + (n*8 + g)*QSTRW;
#pragma unroll
            for (int s = 0; s < 4; ++s) {
                uint32_t bf[2] = { kr[s*8 + tig], kr[s*8 + tig + 4] };
                mma_f16(sc[n], qf[s], bf);
            }
        }

        // ---- online softmax ----
        {
            float mx0 = -1e30f, mx1 = -1e30f;
#pragma unroll
            for (int n = 0; n < 8; ++n) {
                mx0 = fmaxf(mx0, fmaxf(sc[n][0], sc[n][1]));
                mx1 = fmaxf(mx1, fmaxf(sc[n][2], sc[n][3]));
            }
            mx0 = fmaxf(mx0, __shfl_xor_sync(0xffffffffu, mx0, 1));
            mx0 = fmaxf(mx0, __shfl_xor_sync(0xffffffffu, mx0, 2));
            mx1 = fmaxf(mx1, __shfl_xor_sync(0xffffffffu, mx1, 1));
            mx1 = fmaxf(mx1, __shfl_xor_sync(0xffffffffu, mx1, 2));
            float mn0 = fmaxf(m0, mx0), mn1 = fmaxf(m1, mx1);
            float a0 = __expf(m0 - mn0), a1 = __expf(m1 - mn1);
            m0 = mn0; m1 = mn1;
            float rs0 = 0.f, rs1 = 0.f;
#pragma unroll
            for (int n = 0; n < 8; ++n) {
                sc[n][0] = __expf(sc[n][0] - mn0);
                sc[n][1] = __expf(sc[n][1] - mn0);
                sc[n][2] = __expf(sc[n][2] - mn1);
                sc[n][3] = __expf(sc[n][3] - mn1);
                rs0 += sc[n][0] + sc[n][1];
                rs1 += sc[n][2] + sc[n][3];
            }
            rs0 += __shfl_xor_sync(0xffffffffu, rs0, 1);
            rs0 += __shfl_xor_sync(0xffffffffu, rs0, 2);
            rs1 += __shfl_xor_sync(0xffffffffu, rs1, 1);
            rs1 += __shfl_xor_sync(0xffffffffu, rs1, 2);
            l0 = l0*a0 + rs0;
            l1 = l1*a1 + rs1;
#pragma unroll
            for (int n = 0; n < 8; ++n) {
                acc[n][0] *= a0; acc[n][1] *= a0;
                acc[n][2] *= a1; acc[n][3] *= a1;
            }
        }

        // ---- P (fp16) -> per-warp smem ----
#pragma unroll
        for (int n = 0; n < 8; ++n) {
            Pw[ g   *QSTRW + n*4 + tig] = pack_h2(sc[n][0], sc[n][1]);
            Pw[(g+8)*QSTRW + n*4 + tig] = pack_h2(sc[n][2], sc[n][3]);
        }
        __syncwarp();

        // ---- O += P @ V  (V in smem is [hd][kv]) ----
        uint32_t af[4][4];
#pragma unroll
        for (int s = 0; s < 4; ++s) {
            af[s][0] = Pw[ g   *QSTRW + s*8 + tig];
            af[s][1] = Pw[(g+8)*QSTRW + s*8 + tig];
            af[s][2] = Pw[ g   *QSTRW + s*8 + tig + 4];
            af[s][3] = Pw[(g+8)*QSTRW + s*8 + tig + 4];
        }
#pragma unroll
        for (int n = 0; n < 8; ++n) {
            const uint32_t* vr = VsW + (n*8 + g)*QSTRW;
#pragma unroll
            for (int s = 0; s < 4; ++s) {
                uint32_t bf[2] = { vr[s*8 + tig], vr[s*8 + tig + 4] };
                mma_f16(acc[n], af[s], bf);
            }
        }
    }

    // ---- normalize, round to fp16, write ctx [B,S,E] ----
    float inv0 = 1.0f / l0, inv1 = 1.0f / l1;
    int row0 = qb*128 + w*16 + g;
#pragma unroll
    for (int n = 0; n < 8; ++n) {
        int e = h*64 + n*8 + 2*tig;
        uint32_t* d0 = (uint32_t*)(ctx + ((size_t)b*Sq + row0    )*Eq + e);
        uint32_t* d1 = (uint32_t*)(ctx + ((size_t)b*Sq + row0 + 8)*Eq + e);
        *d0 = pack_h2(acc[n][0]*inv0, acc[n][1]*inv0);
        *d1 = pack_h2(acc[n][2]*inv1, acc[n][3]*inv1);
    }
}

// ---------------------------------------------------------------------------
extern "C" void kernel_launch(void* const* d_in, const int* in_sizes, int n_in,
                              void* d_out, int out_size)
{
    const float* q  = (const float*)d_in[0];
    const float* k  = (const float*)d_in[1];
    const float* v  = (const float*)d_in[2];
    const float* Wq = (const float*)d_in[3];
    const float* Wk = (const float*)d_in[4];
    const float* Wv = (const float*)d_in[5];
    const float* Wo = (const float*)d_in[6];
    float* out = (float*)d_out;

    uint16_t *gQ, *gK, *gVT, *gctx, *gqc, *gkc, *gvc, *gwc;
    cudaGetSymbolAddress((void**)&gQ,   g_Q);
    cudaGetSymbolAddress((void**)&gK,   g_K);
    cudaGetSymbolAddress((void**)&gVT,  g_VT);
    cudaGetSymbolAddress((void**)&gctx, g_ctx);
    cudaGetSymbolAddress((void**)&gqc,  g_qc);
    cudaGetSymbolAddress((void**)&gkc,  g_kc);
    cudaGetSymbolAddress((void**)&gvc,  g_vc);
    cudaGetSymbolAddress((void**)&gwc,  g_wc);

    cudaFuncSetAttribute(gemm_h, cudaFuncAttributeMaxDynamicSharedMemorySize,
                         GEMM_SMEM);
    cudaFuncSetAttribute(attn_h, cudaFuncAttributeMaxDynamicSharedMemorySize,
                         ATTN_SMEM);

    // Pre-convert inputs + weights to fp16 (RN)
    const int NB_IN = (Mtot*Eq/4) / 256;   // 4096 blocks
    const int NB_W  = (Eq*Eq/4) / 256;     // 1024 blocks
    cvt_f16<<<NB_IN, 256>>>((const float4*)q, (uint2*)gqc);
    cvt_f16<<<NB_IN, 256>>>((const float4*)k, (uint2*)gkc);
    cvt_f16<<<NB_IN, 256>>>((const float4*)v, (uint2*)gvc);
    cvt_f16<<<NB_W, 256>>>((const float4*)Wq, (uint2*)(gwc + 0*(size_t)Eq*Eq));
    cvt_f16<<<NB_W, 256>>>((const float4*)Wk, (uint2*)(gwc + 1*(size_t)Eq*Eq));
    cvt_f16<<<NB_W, 256>>>((const float4*)Wv, (uint2*)(gwc + 2*(size_t)Eq*Eq));
    cvt_f16<<<NB_W, 256>>>((const float4*)Wo, (uint2*)(gwc + 3*(size_t)Eq*Eq));

    dim3 ggrid(Eq/128, Mtot/128);   // (8, 32) = 256 CTAs, occ 2

    // Projections (softmax scale folded into Q epilogue); V written transposed
    gemm_h<<<ggrid, 256, GEMM_SMEM>>>(gqc, gwc + 0*(size_t)Eq*Eq, gQ,  1, 0.125f);
    gemm_h<<<ggrid, 256, GEMM_SMEM>>>(gkc, gwc + 1*(size_t)Eq*Eq, gK,  1, 1.0f);
    gemm_h<<<ggrid, 256, GEMM_SMEM>>>(gvc, gwc + 2*(size_t)Eq*Eq, gVT, 2, 1.0f);

    attn_h<<<dim3(Sq/128, Hq, Bq), 256, ATTN_SMEM>>>(gQ, gK, gVT, gctx);

    // Output projection straight into d_out (fp32)
    gemm_h<<<ggrid, 256, GEMM_SMEM>>>(gctx, gwc + 3*(size_t)Eq*Eq, out, 0, 1.0f);
}

// round 9
// speedup vs baseline: 7.4491x; 1.2310x over previous
#include <cuda_runtime.h>
#include <cuda_fp16.h>
#include <cstdint>

#define Bq 4
#define Sq 1024
#define Eq 1024
#define Hq 16
#define HDq 64
#define Mtot (Bq*Sq)   // 4096

// Scratch (static device globals: allocation-free). fp16 stored as uint16_t.
__device__ uint16_t g_Q[Bq*Hq*Sq*HDq];    // [B,H,S,HD] fp16
__device__ uint16_t g_K[Bq*Hq*Sq*HDq];    // [B,H,S,HD] fp16
__device__ uint16_t g_VT[Bq*Hq*HDq*Sq];   // [B,H,HD,S] fp16 (transposed V)
__device__ uint16_t g_ctx[Bq*Sq*Eq];      // [B,S,E] fp16
__device__ uint16_t g_qc[Mtot*Eq];        // fp16-rounded inputs
__device__ uint16_t g_kc[Mtot*Eq];
__device__ uint16_t g_vc[Mtot*Eq];
__device__ uint16_t g_wc[4][Eq*Eq];       // fp16-rounded weights

__device__ __forceinline__ uint32_t smem_u32(const void* p) {
    uint32_t a;
    asm("{ .reg .u64 t; cvta.to.shared.u64 t, %1; cvt.u32.u64 %0, t; }"
        : "=r"(a) : "l"(p));
    return a;
}

__device__ __forceinline__ void cp_async16(uint32_t dst, const void* src) {
    asm volatile("cp.async.cg.shared.global [%0], [%1], 16;"
                 :: "r"(dst), "l"(src));
}
#define CP_COMMIT()  asm volatile("cp.async.commit_group;" ::: "memory")
#define CP_WAIT2()   asm volatile("cp.async.wait_group 2;" ::: "memory")
#define CP_WAIT1()   asm volatile("cp.async.wait_group 1;" ::: "memory")

__device__ __forceinline__ void ldsm4(uint32_t* r, uint32_t addr) {
    asm volatile("ldmatrix.sync.aligned.m8n8.x4.shared.b16 {%0,%1,%2,%3}, [%4];"
                 : "=r"(r[0]), "=r"(r[1]), "=r"(r[2]), "=r"(r[3]) : "r"(addr));
}

__device__ __forceinline__ void mma_f16(float c[4], const uint32_t a[4],
                                        const uint32_t b[2]) {
    asm volatile(
        "mma.sync.aligned.m16n8k16.row.col.f32.f16.f16.f32 "
        "{%0,%1,%2,%3}, {%4,%5,%6,%7}, {%8,%9}, {%0,%1,%2,%3};"
        : "+f"(c[0]), "+f"(c[1]), "+f"(c[2]), "+f"(c[3])
        : "r"(a[0]), "r"(a[1]), "r"(a[2]), "r"(a[3]), "r"(b[0]), "r"(b[1]));
}

__device__ __forceinline__ uint32_t pack_h2(float x, float y) {
    __half2 h = __floats2half2_rn(x, y);
    return *(uint32_t*)&h;
}

// ===========================================================================
// fp32 -> fp16 (RN) pre-conversion, batched: grid.y selects tensor
// ===========================================================================
__global__ void __launch_bounds__(256)
cvt3(const float4* __restrict__ s0, const float4* __restrict__ s1,
     const float4* __restrict__ s2,
     uint2* __restrict__ d0, uint2* __restrict__ d1, uint2* __restrict__ d2)
{
    int i = blockIdx.x * 256 + threadIdx.x;
    const float4* s = blockIdx.y == 0 ? s0 : (blockIdx.y == 1 ? s1 : s2);
    uint2*       d = blockIdx.y == 0 ? d0 : (blockIdx.y == 1 ? d1 : d2);
    float4 v = s[i];
    d[i] = make_uint2(pack_h2(v.x, v.y), pack_h2(v.z, v.w));
}

__global__ void __launch_bounds__(256)
cvt4(const float4* __restrict__ s0, const float4* __restrict__ s1,
     const float4* __restrict__ s2, const float4* __restrict__ s3,
     uint2* __restrict__ dst)   // contiguous 4 x Eq*Eq halves
{
    int i = blockIdx.x * 256 + threadIdx.x;
    const float4* s = blockIdx.y == 0 ? s0 : (blockIdx.y == 1 ? s1 :
                      (blockIdx.y == 2 ? s2 : s3));
    float4 v = s[i];
    dst[(size_t)blockIdx.y * (Eq*(size_t)Eq/4) + i] =
        make_uint2(pack_h2(v.x, v.y), pack_h2(v.z, v.w));
}

// ===========================================================================
// fp16 mma.sync NT GEMM with ldmatrix fragment loads.
// C[M,N] = A[M,K] @ W[N,K]^T, K = 1024, fp32 accum. Block 128x128, 8 warps
// (2m x 4n), warp tile 64x32. cp.async 4-stage ring; smem row = 32 halves of
// K, stride 20 words (ldmatrix conflict-free: 20r mod 32 covers all banks).
// remap=0: fp32 row-major; remap=1: fp16 [B,H,S,HD]; remap=2: fp16 [B,H,HD,S].
// ===========================================================================
#define RSTRW 20
#define STAGE_W (128*RSTRW)                // 2560 words per operand-stage
#define GEMM_SMEM (8*STAGE_W*4)            // 81920 B
#define NSTG 32                            // 1024 / 32

__global__ void __launch_bounds__(256, 2)
gemm_h(const uint16_t* __restrict__ A, const uint16_t* __restrict__ W,
       void* __restrict__ Cv, int remap, float scale)
{
    extern __shared__ uint32_t smw[];
    const uint32_t smb = smem_u32(smw);

    const int tid  = threadIdx.x;
    const int wid  = tid >> 5;
    const int lane = tid & 31;
    const int g    = lane >> 2;
    const int tig  = lane & 3;
    const int wm   = (wid & 1) * 64;
    const int wn   = (wid >> 1) * 32;
    const int m0 = blockIdx.y * 128;
    const int n0 = blockIdx.x * 128;

    // staging indices
    const int r0  = tid >> 2;
    const int kc8 = (tid & 3) * 8;

    const uint16_t* Ag = A + (size_t)(m0 + r0) * Eq + kc8;
    const uint16_t* Wg = W + (size_t)(n0 + r0) * Eq + kc8;
    const uint32_t sa = smb + (uint32_t)(r0*RSTRW + (tid & 3)*4) * 4;
    const uint32_t sw = sa + STAGE_W * 4;

    // ldmatrix per-lane bases (word offsets within a stage)
    const int arow = wm + (lane & 15);
    const int akw  = (lane >> 4) << 2;               // 0 or 4
    const int brow = wn + (lane & 7) + ((lane & 16) ? 8 : 0);
    const int bkw  = (lane & 8) ? 4 : 0;
    const uint32_t a_base = smb + (uint32_t)(arow*RSTRW + akw) * 4;
    const uint32_t b_base = smb + (uint32_t)(STAGE_W + brow*RSTRW + bkw) * 4;

    float c[4][4][4];
#pragma unroll
    for (int mt = 0; mt < 4; ++mt)
#pragma unroll
        for (int nt = 0; nt < 4; ++nt)
#pragma unroll
            for (int r = 0; r < 4; ++r) c[mt][nt][r] = 0.f;

    // prologue: stages 0..2
#pragma unroll
    for (int p = 0; p < 3; ++p) {
        uint32_t so = (uint32_t)(p * 2 * STAGE_W * 4);
        int k0 = p * 32;
#pragma unroll
        for (int i = 0; i < 2; ++i) {
            cp_async16(sa + so + i*64*RSTRW*4, Ag + k0 + (size_t)i*64*Eq);
            cp_async16(sw + so + i*64*RSTRW*4, Wg + k0 + (size_t)i*64*Eq);
        }
        CP_COMMIT();
    }

    for (int s = 0; s < NSTG; ++s) {
        CP_WAIT2();
        __syncthreads();

        if (s + 3 < NSTG) {
            uint32_t so = (uint32_t)(((s + 3) & 3) * 2 * STAGE_W * 4);
            int k0 = (s + 3) * 32;
#pragma unroll
            for (int i = 0; i < 2; ++i) {
                cp_async16(sa + so + i*64*RSTRW*4, Ag + k0 + (size_t)i*64*Eq);
                cp_async16(sw + so + i*64*RSTRW*4, Wg + k0 + (size_t)i*64*Eq);
            }
        }
        CP_COMMIT();

        const uint32_t sofs = (uint32_t)((s & 3) * 2 * STAGE_W * 4);

#pragma unroll
        for (int s2 = 0; s2 < 2; ++s2) {   // two k16 slices per stage
            uint32_t af[4][4], bf[4][2];
#pragma unroll
            for (int mt = 0; mt < 4; ++mt)
                ldsm4(af[mt], a_base + sofs +
                      (uint32_t)(mt*16*RSTRW + s2*8) * 4);
#pragma unroll
            for (int ntp = 0; ntp < 2; ++ntp)
                ldsm4(bf[2*ntp], b_base + sofs +
                      (uint32_t)(ntp*16*RSTRW + s2*8) * 4);
#pragma unroll
            for (int mt = 0; mt < 4; ++mt)
#pragma unroll
                for (int nt = 0; nt < 4; ++nt)
                    mma_f16(c[mt][nt], af[mt], bf[nt]);
        }
    }

    // Epilogue
#pragma unroll
    for (int mt = 0; mt < 4; ++mt) {
#pragma unroll
        for (int nt = 0; nt < 4; ++nt) {
            int row0 = m0 + wm + mt*16 + g;
            int col  = n0 + wn + nt*8 + 2*tig;
#pragma unroll
            for (int half = 0; half < 2; ++half) {
                int row = row0 + half*8;
                float v0 = c[mt][nt][half*2+0] * scale;
                float v1 = c[mt][nt][half*2+1] * scale;
                if (remap == 0) {
                    float* dst = (float*)Cv + (size_t)row * Eq + col;
                    *(float2*)dst = make_float2(v0, v1);
                } else if (remap == 1) {
                    int b = row >> 10, s = row & 1023;
                    int h = col >> 6, d = col & 63;
                    uint32_t* dst = (uint32_t*)((uint16_t*)Cv +
                        ((((size_t)(b*Hq + h))*Sq + s)*HDq + d));
                    *dst = pack_h2(v0, v1);
                } else {
                    int b = row >> 10, s = row & 1023;
                    int h = col >> 6, d = col & 63;
                    uint16_t* dst = (uint16_t*)Cv +
                        (((size_t)(b*Hq + h))*HDq + d)*Sq + s;
                    __half h0 = __float2half_rn(v0);
                    __half h1 = __float2half_rn(v1);
                    dst[0]  = *(uint16_t*)&h0;
                    dst[Sq] = *(uint16_t*)&h1;
                }
            }
        }
    }
}

// ===========================================================================
// fp16 mma.sync flash attention, ldmatrix + register-resident P (FA2 style).
// Q/K fp16 [B,H,S,HD]; V fp16 transposed [B,H,HD,S].
// Block = 128 q rows x (head, batch); 8 warps x 16 q rows.
// K/V double-buffered cp.async. S C-fragments repacked directly into PV
// A-fragments (no P smem roundtrip). smem rows stride 36 words.
// ===========================================================================
#define QSTRW 36
#define TILE_W (64*QSTRW)                  // 2304 words (one K or V tile)
#define BUF_W (2*TILE_W)                   // K+V per buffer
#define PQ_W (128*QSTRW)                   // Q staging region
#define ATTN_SMEM ((2*BUF_W + PQ_W)*4)     // 55296 B

__global__ void __launch_bounds__(256, 2)
attn_h(const uint16_t* __restrict__ Qg, const uint16_t* __restrict__ Kg,
       const uint16_t* __restrict__ VTg, uint16_t* __restrict__ ctx)
{
    extern __shared__ uint32_t smw[];
    uint32_t* Pq = smw + 2*BUF_W;
    const uint32_t smb = smem_u32(smw);

    const int tid  = threadIdx.x;
    const int w    = tid >> 5;
    const int lane = tid & 31;
    const int g    = lane >> 2;
    const int tig  = lane & 3;
    const int qb = blockIdx.x, h = blockIdx.y, b = blockIdx.z;

    const uint16_t* Qp  = Qg  + (((size_t)(b*Hq + h))*Sq + qb*128) * HDq;
    const uint16_t* Kp  = Kg  + ((size_t)(b*Hq + h))*Sq*HDq;
    const uint16_t* VTp = VTg + ((size_t)(b*Hq + h))*HDq*Sq;

    auto issue_tile = [&](int kt) {
        uint32_t kb = smb + (uint32_t)((kt & 1) * BUF_W * 4);
        uint32_t vb = kb + TILE_W * 4;
#pragma unroll
        for (int i = 0; i < 2; ++i) {
            int idx = tid + i*256;
            int r = idx >> 3, c8 = idx & 7;
            uint32_t so = (uint32_t)((r*QSTRW + c8*4) * 4);
            cp_async16(kb + so, Kp + (size_t)(kt*64 + r)*HDq + c8*8);
            cp_async16(vb + so, VTp + (size_t)r*Sq + kt*64 + c8*8);
        }
    };

    issue_tile(0);
    CP_COMMIT();

    // ---- Stage Q (fp16) into Pq region [128][36w] ----
    {
        const uint4* Q4 = (const uint4*)Qp;
#pragma unroll
        for (int i = 0; i < 4; ++i) {
            int idx = tid + i*256;
            int r = idx >> 3, c8 = idx & 7;
            *(uint4*)(Pq + r*QSTRW + c8*4) = Q4[idx];
        }
    }
    __syncthreads();

    // Q fragments via ldmatrix (rows w*16 + lane&15)
    uint32_t qf[4][4];
    {
        const int qrow = w*16 + (lane & 15);
        const uint32_t q_base = smb +
            (uint32_t)((2*BUF_W) + qrow*QSTRW + ((lane >> 4) << 2)) * 4;
#pragma unroll
        for (int s = 0; s < 4; ++s)
            ldsm4(qf[s], q_base + (uint32_t)(s*8) * 4);
    }

    // ldmatrix per-lane base for K/V tiles (B-operand pattern)
    const int kvrow = (lane & 7) + ((lane & 16) ? 8 : 0);
    const int kvkw  = (lane & 8) ? 4 : 0;
    const uint32_t kv_lane_off = (uint32_t)(kvrow*QSTRW + kvkw) * 4;

    float acc[8][4];
#pragma unroll
    for (int n = 0; n < 8; ++n)
#pragma unroll
        for (int r = 0; r < 4; ++r) acc[n][r] = 0.f;
    float m0 = -1e30f, m1 = -1e30f, l0 = 0.f, l1 = 0.f;

    for (int kt = 0; kt < 16; ++kt) {
        __syncthreads();   // prior buffer reads retired
        if (kt + 1 < 16) issue_tile(kt + 1);
        CP_COMMIT();
        CP_WAIT1();        // tile kt resident; kt+1 in flight
        __syncthreads();

        const uint32_t kbase = smb + (uint32_t)((kt & 1) * BUF_W * 4)
                             + kv_lane_off;
        const uint32_t vbase = kbase + (uint32_t)TILE_W * 4;

        // ---- S = Q @ K^T ----
        float sc[8][4];
#pragma unroll
        for (int n = 0; n < 8; ++n)
#pragma unroll
            for (int r = 0; r < 4; ++r) sc[n][r] = 0.f;
#pragma unroll
        for (int s = 0; s < 4; ++s) {
            uint32_t kf[8][2];
#pragma unroll
            for (int ntp = 0; ntp < 4; ++ntp)
                ldsm4(kf[2*ntp], kbase + (uint32_t)(ntp*16*QSTRW + s*8) * 4);
#pragma unroll
            for (int n = 0; n < 8; ++n)
                mma_f16(sc[n], qf[s], kf[n]);
        }

        // ---- online softmax ----
        {
            float mx0 = -1e30f, mx1 = -1e30f;
#pragma unroll
            for (int n = 0; n < 8; ++n) {
                mx0 = fmaxf(mx0, fmaxf(sc[n][0], sc[n][1]));
                mx1 = fmaxf(mx1, fmaxf(sc[n][2], sc[n][3]));
            }
            mx0 = fmaxf(mx0, __shfl_xor_sync(0xffffffffu, mx0, 1));
            mx0 = fmaxf(mx0, __shfl_xor_sync(0xffffffffu, mx0, 2));
            mx1 = fmaxf(mx1, __shfl_xor_sync(0xffffffffu, mx1, 1));
            mx1 = fmaxf(mx1, __shfl_xor_sync(0xffffffffu, mx1, 2));
            float mn0 = fmaxf(m0, mx0), mn1 = fmaxf(m1, mx1);
            float a0 = __expf(m0 - mn0), a1 = __expf(m1 - mn1);
            m0 = mn0; m1 = mn1;
            float rs0 = 0.f, rs1 = 0.f;
#pragma unroll
            for (int n = 0; n < 8; ++n) {
                sc[n][0] = __expf(sc[n][0] - mn0);
                sc[n][1] = __expf(sc[n][1] - mn0);
                sc[n][2] = __expf(sc[n][2] - mn1);
                sc[n][3] = __expf(sc[n][3] - mn1);
                rs0 += sc[n][0] + sc[n][1];
                rs1 += sc[n][2] + sc[n][3];
            }
            rs0 += __shfl_xor_sync(0xffffffffu, rs0, 1);
            rs0 += __shfl_xor_sync(0xffffffffu, rs0, 2);
            rs1 += __shfl_xor_sync(0xffffffffu, rs1, 1);
            rs1 += __shfl_xor_sync(0xffffffffu, rs1, 2);
            l0 = l0*a0 + rs0;
            l1 = l1*a1 + rs1;
#pragma unroll
            for (int n = 0; n < 8; ++n) {
                acc[n][0] *= a0; acc[n][1] *= a0;
                acc[n][2] *= a1; acc[n][3] *= a1;
            }
        }

        // ---- P A-fragments directly from S C-fragments (no smem) ----
        uint32_t af[4][4];
#pragma unroll
        for (int s = 0; s < 4; ++s) {
            af[s][0] = pack_h2(sc[2*s  ][0], sc[2*s  ][1]);
            af[s][1] = pack_h2(sc[2*s  ][2], sc[2*s  ][3]);
            af[s][2] = pack_h2(sc[2*s+1][0], sc[2*s+1][1]);
            af[s][3] = pack_h2(sc[2*s+1][2], sc[2*s+1][3]);
        }

        // ---- O += P @ V  (V smem is [hd][kv]) ----
#pragma unroll
        for (int s = 0; s < 4; ++s) {
            uint32_t vf[8][2];
#pragma unroll
            for (int ntp = 0; ntp < 4; ++ntp)
                ldsm4(vf[2*ntp], vbase + (uint32_t)(ntp*16*QSTRW + s*8) * 4);
#pragma unroll
            for (int n = 0; n < 8; ++n)
                mma_f16(acc[n], af[s], vf[n]);
        }
    }

    // ---- normalize, round to fp16, write ctx [B,S,E] ----
    float inv0 = 1.0f / l0, inv1 = 1.0f / l1;
    int row0 = qb*128 + w*16 + g;
#pragma unroll
    for (int n = 0; n < 8; ++n) {
        int e = h*64 + n*8 + 2*tig;
        uint32_t* d0 = (uint32_t*)(ctx + ((size_t)b*Sq + row0    )*Eq + e);
        uint32_t* d1 = (uint32_t*)(ctx + ((size_t)b*Sq + row0 + 8)*Eq + e);
        *d0 = pack_h2(acc[n][0]*inv0, acc[n][1]*inv0);
        *d1 = pack_h2(acc[n][2]*inv1, acc[n][3]*inv1);
    }
}

// ---------------------------------------------------------------------------
extern "C" void kernel_launch(void* const* d_in, const int* in_sizes, int n_in,
                              void* d_out, int out_size)
{
    const float* q  = (const float*)d_in[0];
    const float* k  = (const float*)d_in[1];
    const float* v  = (const float*)d_in[2];
    const float* Wq = (const float*)d_in[3];
    const float* Wk = (const float*)d_in[4];
    const float* Wv = (const float*)d_in[5];
    const float* Wo = (const float*)d_in[6];
    float* out = (float*)d_out;

    uint16_t *gQ, *gK, *gVT, *gctx, *gqc, *gkc, *gvc, *gwc;
    cudaGetSymbolAddress((void**)&gQ,   g_Q);
    cudaGetSymbolAddress((void**)&gK,   g_K);
    cudaGetSymbolAddress((void**)&gVT,  g_VT);
    cudaGetSymbolAddress((void**)&gctx, g_ctx);
    cudaGetSymbolAddress((void**)&gqc,  g_qc);
    cudaGetSymbolAddress((void**)&gkc,  g_kc);
    cudaGetSymbolAddress((void**)&gvc,  g_vc);
    cudaGetSymbolAddress((void**)&gwc,  g_wc);

    cudaFuncSetAttribute(gemm_h, cudaFuncAttributeMaxDynamicSharedMemorySize,
                         GEMM_SMEM);
    cudaFuncSetAttribute(attn_h, cudaFuncAttributeMaxDynamicSharedMemorySize,
                         ATTN_SMEM);

    // Pre-convert inputs + weights to fp16 (RN), 2 batched launches
    cvt3<<<dim3((Mtot*Eq/4)/256, 3), 256>>>(
        (const float4*)q, (const float4*)k, (const float4*)v,
        (uint2*)gqc, (uint2*)gkc, (uint2*)gvc);
    cvt4<<<dim3((Eq*Eq/4)/256, 4), 256>>>(
        (const float4*)Wq, (const float4*)Wk, (const float4*)Wv,
        (const float4*)Wo, (uint2*)gwc);

    dim3 ggrid(Eq/128, Mtot/128);   // (8, 32) = 256 CTAs, occ 2

    // Projections (softmax scale folded into Q epilogue); V written transposed
    gemm_h<<<ggrid, 256, GEMM_SMEM>>>(gqc, gwc + 0*(size_t)Eq*Eq, gQ,  1, 0.125f);
    gemm_h<<<ggrid, 256, GEMM_SMEM>>>(gkc, gwc + 1*(size_t)Eq*Eq, gK,  1, 1.0f);
    gemm_h<<<ggrid, 256, GEMM_SMEM>>>(gvc, gwc + 2*(size_t)Eq*Eq, gVT, 2, 1.0f);

    attn_h<<<dim3(Sq/128, Hq, Bq), 256, ATTN_SMEM>>>(gQ, gK, gVT, gctx);

    // Output projection straight into d_out (fp32)
    gemm_h<<<ggrid, 256, GEMM_SMEM>>>(gctx, gwc + 3*(size_t)Eq*Eq, out, 0, 1.0f);
}

// round 10
// speedup vs baseline: 7.8005x; 1.0472x over previous
#include <cuda_runtime.h>
#include <cuda_fp16.h>
#include <cstdint>

#define Bq 4
#define Sq 1024
#define Eq 1024
#define Hq 16
#define HDq 64
#define Mtot (Bq*Sq)   // 4096

// Q projection scale: (1/sqrt(64)) * log2(e)  — softmax runs in exp2 domain
#define QSCALE 0.18033688011f

// Scratch (static device globals: allocation-free). fp16 stored as uint16_t.
__device__ uint16_t g_Q[Bq*Hq*Sq*HDq];    // [B,H,S,HD] fp16 (pre-scaled)
__device__ uint16_t g_K[Bq*Hq*Sq*HDq];    // [B,H,S,HD] fp16
__device__ uint16_t g_VT[Bq*Hq*HDq*Sq];   // [B,H,HD,S] fp16 (transposed V)
__device__ uint16_t g_ctx[Bq*Sq*Eq];      // [B,S,E] fp16
__device__ uint16_t g_qc[Mtot*Eq];        // fp16-rounded inputs
__device__ uint16_t g_kc[Mtot*Eq];
__device__ uint16_t g_vc[Mtot*Eq];
__device__ uint16_t g_wc[4][Eq*Eq];       // fp16-rounded weights

__device__ __forceinline__ uint32_t smem_u32(const void* p) {
    uint32_t a;
    asm("{ .reg .u64 t; cvta.to.shared.u64 t, %1; cvt.u32.u64 %0, t; }"
        : "=r"(a) : "l"(p));
    return a;
}

__device__ __forceinline__ void cp_async16(uint32_t dst, const void* src) {
    asm volatile("cp.async.cg.shared.global [%0], [%1], 16;"
                 :: "r"(dst), "l"(src));
}
#define CP_COMMIT()  asm volatile("cp.async.commit_group;" ::: "memory")
#define CP_WAIT2()   asm volatile("cp.async.wait_group 2;" ::: "memory")
#define CP_WAIT1()   asm volatile("cp.async.wait_group 1;" ::: "memory")

__device__ __forceinline__ void ldsm4(uint32_t* r, uint32_t addr) {
    asm volatile("ldmatrix.sync.aligned.m8n8.x4.shared.b16 {%0,%1,%2,%3}, [%4];"
                 : "=r"(r[0]), "=r"(r[1]), "=r"(r[2]), "=r"(r[3]) : "r"(addr));
}

__device__ __forceinline__ void mma_f16(float c[4], const uint32_t a[4],
                                        const uint32_t b[2]) {
    asm volatile(
        "mma.sync.aligned.m16n8k16.row.col.f32.f16.f16.f32 "
        "{%0,%1,%2,%3}, {%4,%5,%6,%7}, {%8,%9}, {%0,%1,%2,%3};"
        : "+f"(c[0]), "+f"(c[1]), "+f"(c[2]), "+f"(c[3])
        : "r"(a[0]), "r"(a[1]), "r"(a[2]), "r"(a[3]), "r"(b[0]), "r"(b[1]));
}

__device__ __forceinline__ uint32_t pack_h2(float x, float y) {
    __half2 h = __floats2half2_rn(x, y);
    return *(uint32_t*)&h;
}

__device__ __forceinline__ float ex2(float x) {
    float r;
    asm("ex2.approx.f32 %0, %1;" : "=f"(r) : "f"(x));
    return r;
}

// ===========================================================================
// fp32 -> fp16 (RN) pre-conversion, batched
// ===========================================================================
__global__ void __launch_bounds__(256)
cvt3(const float4* __restrict__ s0, const float4* __restrict__ s1,
     const float4* __restrict__ s2,
     uint2* __restrict__ d0, uint2* __restrict__ d1, uint2* __restrict__ d2)
{
    int i = blockIdx.x * 256 + threadIdx.x;
    const float4* s = blockIdx.y == 0 ? s0 : (blockIdx.y == 1 ? s1 : s2);
    uint2*       d = blockIdx.y == 0 ? d0 : (blockIdx.y == 1 ? d1 : d2);
    float4 v = s[i];
    d[i] = make_uint2(pack_h2(v.x, v.y), pack_h2(v.z, v.w));
}

__global__ void __launch_bounds__(256)
cvt4(const float4* __restrict__ s0, const float4* __restrict__ s1,
     const float4* __restrict__ s2, const float4* __restrict__ s3,
     uint2* __restrict__ dst)
{
    int i = blockIdx.x * 256 + threadIdx.x;
    const float4* s = blockIdx.y == 0 ? s0 : (blockIdx.y == 1 ? s1 :
                      (blockIdx.y == 2 ? s2 : s3));
    float4 v = s[i];
    dst[(size_t)blockIdx.y * (Eq*(size_t)Eq/4) + i] =
        make_uint2(pack_h2(v.x, v.y), pack_h2(v.z, v.w));
}

// ===========================================================================
// GEMM core (device inline): one 128x128 tile of C = A @ W^T, K=1024.
// 8 warps (2m x 4n), warp tile 64x32, cp.async 4-stage ring, ldmatrix frags.
// ===========================================================================
#define RSTRW 20
#define STAGE_W (128*RSTRW)
#define GEMM_SMEM (8*STAGE_W*4)            // 81920 B
#define NSTG 32

struct GemmOut { float c[4][4][4]; };

__device__ __forceinline__ void gemm_core(
    const uint16_t* __restrict__ A, const uint16_t* __restrict__ W,
    uint32_t* smw, int m0, int n0, float c[4][4][4])
{
    const uint32_t smb = smem_u32(smw);
    const int tid  = threadIdx.x;
    const int wid  = tid >> 5;
    const int lane = tid & 31;
    const int wm   = (wid & 1) * 64;
    const int wn   = (wid >> 1) * 32;

    const int r0  = tid >> 2;
    const int kc8 = (tid & 3) * 8;

    const uint16_t* Ag = A + (size_t)(m0 + r0) * Eq + kc8;
    const uint16_t* Wg = W + (size_t)(n0 + r0) * Eq + kc8;
    const uint32_t sa = smb + (uint32_t)(r0*RSTRW + (tid & 3)*4) * 4;
    const uint32_t sw = sa + STAGE_W * 4;

    const int arow = wm + (lane & 15);
    const int akw  = (lane >> 4) << 2;
    const int brow = wn + (lane & 7) + ((lane & 16) ? 8 : 0);
    const int bkw  = (lane & 8) ? 4 : 0;
    const uint32_t a_base = smb + (uint32_t)(arow*RSTRW + akw) * 4;
    const uint32_t b_base = smb + (uint32_t)(STAGE_W + brow*RSTRW + bkw) * 4;

#pragma unroll
    for (int mt = 0; mt < 4; ++mt)
#pragma unroll
        for (int nt = 0; nt < 4; ++nt)
#pragma unroll
            for (int r = 0; r < 4; ++r) c[mt][nt][r] = 0.f;

#pragma unroll
    for (int p = 0; p < 3; ++p) {
        uint32_t so = (uint32_t)(p * 2 * STAGE_W * 4);
        int k0 = p * 32;
#pragma unroll
        for (int i = 0; i < 2; ++i) {
            cp_async16(sa + so + i*64*RSTRW*4, Ag + k0 + (size_t)i*64*Eq);
            cp_async16(sw + so + i*64*RSTRW*4, Wg + k0 + (size_t)i*64*Eq);
        }
        CP_COMMIT();
    }

    for (int s = 0; s < NSTG; ++s) {
        CP_WAIT2();
        __syncthreads();

        if (s + 3 < NSTG) {
            uint32_t so = (uint32_t)(((s + 3) & 3) * 2 * STAGE_W * 4);
            int k0 = (s + 3) * 32;
#pragma unroll
            for (int i = 0; i < 2; ++i) {
                cp_async16(sa + so + i*64*RSTRW*4, Ag + k0 + (size_t)i*64*Eq);
                cp_async16(sw + so + i*64*RSTRW*4, Wg + k0 + (size_t)i*64*Eq);
            }
        }
        CP_COMMIT();

        const uint32_t sofs = (uint32_t)((s & 3) * 2 * STAGE_W * 4);

#pragma unroll
        for (int s2 = 0; s2 < 2; ++s2) {
            uint32_t af[4][4], bf[4][2];
#pragma unroll
            for (int ntp = 0; ntp < 2; ++ntp)
                ldsm4(bf[2*ntp], b_base + sofs +
                      (uint32_t)(ntp*16*RSTRW + s2*8) * 4);
#pragma unroll
            for (int mt = 0; mt < 4; ++mt)
                ldsm4(af[mt], a_base + sofs +
                      (uint32_t)(mt*16*RSTRW + s2*8) * 4);
#pragma unroll
            for (int mt = 0; mt < 4; ++mt)
#pragma unroll
                for (int nt = 0; nt < 4; ++nt)
                    mma_f16(c[mt][nt], af[mt], bf[nt]);
        }
    }
}

// ===========================================================================
// Merged QKV projection GEMM: grid.z = 0(Q)/1(K)/2(V-transposed).
// ===========================================================================
__global__ void __launch_bounds__(256, 2)
gemm_qkv(const uint16_t* __restrict__ qc, const uint16_t* __restrict__ kc,
         const uint16_t* __restrict__ vc, const uint16_t* __restrict__ wc,
         uint16_t* __restrict__ Qo, uint16_t* __restrict__ Ko,
         uint16_t* __restrict__ VTo)
{
    extern __shared__ uint32_t smw[];
    const int z = blockIdx.z;
    const uint16_t* A = z == 0 ? qc : (z == 1 ? kc : vc);
    const uint16_t* W = wc + (size_t)z * Eq * Eq;
    const float scale = (z == 0) ? QSCALE : 1.0f;
    const int m0 = blockIdx.y * 128;
    const int n0 = blockIdx.x * 128;

    float c[4][4][4];
    gemm_core(A, W, smw, m0, n0, c);

    const int tid  = threadIdx.x;
    const int wid  = tid >> 5;
    const int lane = tid & 31;
    const int g    = lane >> 2;
    const int tig  = lane & 3;
    const int wm   = (wid & 1) * 64;
    const int wn   = (wid >> 1) * 32;

#pragma unroll
    for (int mt = 0; mt < 4; ++mt) {
#pragma unroll
        for (int nt = 0; nt < 4; ++nt) {
            int row0 = m0 + wm + mt*16 + g;
            int col  = n0 + wn + nt*8 + 2*tig;
#pragma unroll
            for (int half = 0; half < 2; ++half) {
                int row = row0 + half*8;
                float v0 = c[mt][nt][half*2+0] * scale;
                float v1 = c[mt][nt][half*2+1] * scale;
                int b = row >> 10, s = row & 1023;
                int h = col >> 6, d = col & 63;
                if (z < 2) {
                    uint16_t* base = z == 0 ? Qo : Ko;
                    uint32_t* dst = (uint32_t*)(base +
                        ((((size_t)(b*Hq + h))*Sq + s)*HDq + d));
                    *dst = pack_h2(v0, v1);
                } else {
                    uint16_t* dst = VTo +
                        (((size_t)(b*Hq + h))*HDq + d)*Sq + s;
                    __half h0 = __float2half_rn(v0);
                    __half h1 = __float2half_rn(v1);
                    dst[0]  = *(uint16_t*)&h0;
                    dst[Sq] = *(uint16_t*)&h1;
                }
            }
        }
    }
}

// ===========================================================================
// Output projection GEMM: fp32 row-major straight to d_out.
// ===========================================================================
__global__ void __launch_bounds__(256, 2)
gemm_out(const uint16_t* __restrict__ A, const uint16_t* __restrict__ W,
         float* __restrict__ C)
{
    extern __shared__ uint32_t smw[];
    const int m0 = blockIdx.y * 128;
    const int n0 = blockIdx.x * 128;

    float c[4][4][4];
    gemm_core(A, W, smw, m0, n0, c);

    const int tid  = threadIdx.x;
    const int wid  = tid >> 5;
    const int lane = tid & 31;
    const int g    = lane >> 2;
    const int tig  = lane & 3;
    const int wm   = (wid & 1) * 64;
    const int wn   = (wid >> 1) * 32;

#pragma unroll
    for (int mt = 0; mt < 4; ++mt) {
#pragma unroll
        for (int nt = 0; nt < 4; ++nt) {
            int row0 = m0 + wm + mt*16 + g;
            int col  = n0 + wn + nt*8 + 2*tig;
#pragma unroll
            for (int half = 0; half < 2; ++half) {
                int row = row0 + half*8;
                float* dst = C + (size_t)row * Eq + col;
                *(float2*)dst = make_float2(c[mt][nt][half*2+0],
                                            c[mt][nt][half*2+1]);
            }
        }
    }
}

// ===========================================================================
// fp16 mma.sync flash attention (exp2 domain; Q pre-scaled by 1/8*log2e).
// ===========================================================================
#define QSTRW 36
#define TILE_W (64*QSTRW)
#define BUF_W (2*TILE_W)
#define PQ_W (128*QSTRW)
#define ATTN_SMEM ((2*BUF_W + PQ_W)*4)     // 55296 B

__global__ void __launch_bounds__(256, 2)
attn_h(const uint16_t* __restrict__ Qg, const uint16_t* __restrict__ Kg,
       const uint16_t* __restrict__ VTg, uint16_t* __restrict__ ctx)
{
    extern __shared__ uint32_t smw[];
    uint32_t* Pq = smw + 2*BUF_W;
    const uint32_t smb = smem_u32(smw);

    const int tid  = threadIdx.x;
    const int w    = tid >> 5;
    const int lane = tid & 31;
    const int g    = lane >> 2;
    const int tig  = lane & 3;
    const int qb = blockIdx.x, h = blockIdx.y, b = blockIdx.z;

    const uint16_t* Qp  = Qg  + (((size_t)(b*Hq + h))*Sq + qb*128) * HDq;
    const uint16_t* Kp  = Kg  + ((size_t)(b*Hq + h))*Sq*HDq;
    const uint16_t* VTp = VTg + ((size_t)(b*Hq + h))*HDq*Sq;

    auto issue_tile = [&](int kt) {
        uint32_t kb = smb + (uint32_t)((kt & 1) * BUF_W * 4);
        uint32_t vb = kb + TILE_W * 4;
#pragma unroll
        for (int i = 0; i < 2; ++i) {
            int idx = tid + i*256;
            int r = idx >> 3, c8 = idx & 7;
            uint32_t so = (uint32_t)((r*QSTRW + c8*4) * 4);
            cp_async16(kb + so, Kp + (size_t)(kt*64 + r)*HDq + c8*8);
            cp_async16(vb + so, VTp + (size_t)r*Sq + kt*64 + c8*8);
        }
    };

    issue_tile(0);
    CP_COMMIT();

    {
        const uint4* Q4 = (const uint4*)Qp;
#pragma unroll
        for (int i = 0; i < 4; ++i) {
            int idx = tid + i*256;
            int r = idx >> 3, c8 = idx & 7;
            *(uint4*)(Pq + r*QSTRW + c8*4) = Q4[idx];
        }
    }
    __syncthreads();

    uint32_t qf[4][4];
    {
        const int qrow = w*16 + (lane & 15);
        const uint32_t q_base = smb +
            (uint32_t)((2*BUF_W) + qrow*QSTRW + ((lane >> 4) << 2)) * 4;
#pragma unroll
        for (int s = 0; s < 4; ++s)
            ldsm4(qf[s], q_base + (uint32_t)(s*8) * 4);
    }

    const int kvrow = (lane & 7) + ((lane & 16) ? 8 : 0);
    const int kvkw  = (lane & 8) ? 4 : 0;
    const uint32_t kv_lane_off = (uint32_t)(kvrow*QSTRW + kvkw) * 4;

    float acc[8][4];
#pragma unroll
    for (int n = 0; n < 8; ++n)
#pragma unroll
        for (int r = 0; r < 4; ++r) acc[n][r] = 0.f;
    float m0 = -1e30f, m1 = -1e30f, l0 = 0.f, l1 = 0.f;

    for (int kt = 0; kt < 16; ++kt) {
        __syncthreads();
        if (kt + 1 < 16) issue_tile(kt + 1);
        CP_COMMIT();
        CP_WAIT1();
        __syncthreads();

        const uint32_t kbase = smb + (uint32_t)((kt & 1) * BUF_W * 4)
                             + kv_lane_off;
        const uint32_t vbase = kbase + (uint32_t)TILE_W * 4;

        // ---- S = Q @ K^T (log2-domain scores) ----
        float sc[8][4];
#pragma unroll
        for (int n = 0; n < 8; ++n)
#pragma unroll
            for (int r = 0; r < 4; ++r) sc[n][r] = 0.f;
#pragma unroll
        for (int s = 0; s < 4; ++s) {
            uint32_t kf[8][2];
#pragma unroll
            for (int ntp = 0; ntp < 4; ++ntp)
                ldsm4(kf[2*ntp], kbase + (uint32_t)(ntp*16*QSTRW + s*8) * 4);
#pragma unroll
            for (int n = 0; n < 8; ++n)
                mma_f16(sc[n], qf[s], kf[n]);
        }

        // ---- online softmax in exp2 domain ----
        {
            float mx0 = -1e30f, mx1 = -1e30f;
#pragma unroll
            for (int n = 0; n < 8; ++n) {
                mx0 = fmaxf(mx0, fmaxf(sc[n][0], sc[n][1]));
                mx1 = fmaxf(mx1, fmaxf(sc[n][2], sc[n][3]));
            }
            mx0 = fmaxf(mx0, __shfl_xor_sync(0xffffffffu, mx0, 1));
            mx0 = fmaxf(mx0, __shfl_xor_sync(0xffffffffu, mx0, 2));
            mx1 = fmaxf(mx1, __shfl_xor_sync(0xffffffffu, mx1, 1));
            mx1 = fmaxf(mx1, __shfl_xor_sync(0xffffffffu, mx1, 2));
            float mn0 = fmaxf(m0, mx0), mn1 = fmaxf(m1, mx1);
            float a0 = ex2(m0 - mn0), a1 = ex2(m1 - mn1);
            m0 = mn0; m1 = mn1;
            float rs0 = 0.f, rs1 = 0.f;
#pragma unroll
            for (int n = 0; n < 8; ++n) {
                sc[n][0] = ex2(sc[n][0] - mn0);
                sc[n][1] = ex2(sc[n][1] - mn0);
                sc[n][2] = ex2(sc[n][2] - mn1);
                sc[n][3] = ex2(sc[n][3] - mn1);
                rs0 += sc[n][0] + sc[n][1];
                rs1 += sc[n][2] + sc[n][3];
            }
            rs0 += __shfl_xor_sync(0xffffffffu, rs0, 1);
            rs0 += __shfl_xor_sync(0xffffffffu, rs0, 2);
            rs1 += __shfl_xor_sync(0xffffffffu, rs1, 1);
            rs1 += __shfl_xor_sync(0xffffffffu, rs1, 2);
            l0 = l0*a0 + rs0;
            l1 = l1*a1 + rs1;
#pragma unroll
            for (int n = 0; n < 8; ++n) {
                acc[n][0] *= a0; acc[n][1] *= a0;
                acc[n][2] *= a1; acc[n][3] *= a1;
            }
        }

        // ---- P A-fragments directly from S C-fragments ----
        uint32_t af[4][4];
#pragma unroll
        for (int s = 0; s < 4; ++s) {
            af[s][0] = pack_h2(sc[2*s  ][0], sc[2*s  ][1]);
            af[s][1] = pack_h2(sc[2*s  ][2], sc[2*s  ][3]);
            af[s][2] = pack_h2(sc[2*s+1][0], sc[2*s+1][1]);
            af[s][3] = pack_h2(sc[2*s+1][2], sc[2*s+1][3]);
        }

        // ---- O += P @ V ----
#pragma unroll
        for (int s = 0; s < 4; ++s) {
            uint32_t vf[8][2];
#pragma unroll
            for (int ntp = 0; ntp < 4; ++ntp)
                ldsm4(vf[2*ntp], vbase + (uint32_t)(ntp*16*QSTRW + s*8) * 4);
#pragma unroll
            for (int n = 0; n < 8; ++n)
                mma_f16(acc[n], af[s], vf[n]);
        }
    }

    float inv0 = 1.0f / l0, inv1 = 1.0f / l1;
    int row0 = qb*128 + w*16 + g;
#pragma unroll
    for (int n = 0; n < 8; ++n) {
        int e = h*64 + n*8 + 2*tig;
        uint32_t* d0 = (uint32_t*)(ctx + ((size_t)b*Sq + row0    )*Eq + e);
        uint32_t* d1 = (uint32_t*)(ctx + ((size_t)b*Sq + row0 + 8)*Eq + e);
        *d0 = pack_h2(acc[n][0]*inv0, acc[n][1]*inv0);
        *d1 = pack_h2(acc[n][2]*inv1, acc[n][3]*inv1);
    }
}

// ---------------------------------------------------------------------------
extern "C" void kernel_launch(void* const* d_in, const int* in_sizes, int n_in,
                              void* d_out, int out_size)
{
    const float* q  = (const float*)d_in[0];
    const float* k  = (const float*)d_in[1];
    const float* v  = (const float*)d_in[2];
    const float* Wq = (const float*)d_in[3];
    const float* Wk = (const float*)d_in[4];
    const float* Wv = (const float*)d_in[5];
    const float* Wo = (const float*)d_in[6];
    float* out = (float*)d_out;

    uint16_t *gQ, *gK, *gVT, *gctx, *gqc, *gkc, *gvc, *gwc;
    cudaGetSymbolAddress((void**)&gQ,   g_Q);
    cudaGetSymbolAddress((void**)&gK,   g_K);
    cudaGetSymbolAddress((void**)&gVT,  g_VT);
    cudaGetSymbolAddress((void**)&gctx, g_ctx);
    cudaGetSymbolAddress((void**)&gqc,  g_qc);
    cudaGetSymbolAddress((void**)&gkc,  g_kc);
    cudaGetSymbolAddress((void**)&gvc,  g_vc);
    cudaGetSymbolAddress((void**)&gwc,  g_wc);

    cudaFuncSetAttribute(gemm_qkv, cudaFuncAttributeMaxDynamicSharedMemorySize,
                         GEMM_SMEM);
    cudaFuncSetAttribute(gemm_out, cudaFuncAttributeMaxDynamicSharedMemorySize,
                         GEMM_SMEM);
    cudaFuncSetAttribute(attn_h, cudaFuncAttributeMaxDynamicSharedMemorySize,
                         ATTN_SMEM);

    // Pre-convert inputs + weights to fp16 (RN), 2 batched launches
    cvt3<<<dim3((Mtot*Eq/4)/256, 3), 256>>>(
        (const float4*)q, (const float4*)k, (const float4*)v,
        (uint2*)gqc, (uint2*)gkc, (uint2*)gvc);
    cvt4<<<dim3((Eq*Eq/4)/256, 4), 256>>>(
        (const float4*)Wq, (const float4*)Wk, (const float4*)Wv,
        (const float4*)Wo, (uint2*)gwc);

    // Merged QKV projections: 768 CTAs in one launch
    gemm_qkv<<<dim3(Eq/128, Mtot/128, 3), 256, GEMM_SMEM>>>(
        gqc, gkc, gvc, gwc, gQ, gK, gVT);

    attn_h<<<dim3(Sq/128, Hq, Bq), 256, ATTN_SMEM>>>(gQ, gK, gVT, gctx);

    // Output projection straight into d_out (fp32)
    gemm_out<<<dim3(Eq/128, Mtot/128), 256, GEMM_SMEM>>>(
        gctx, gwc + 3*(size_t)Eq*Eq, out);
}

// round 11
// speedup vs baseline: 8.3065x; 1.0649x over previous
#include <cuda_runtime.h>
#include <cuda_fp16.h>
#include <cstdint>

#define Bq 4
#define Sq 1024
#define Eq 1024
#define Hq 16
#define HDq 64
#define Mtot (Bq*Sq)   // 4096

// Q projection scale: (1/sqrt(64)) * log2(e)  — softmax runs in exp2 domain
#define QSCALE 0.18033688011f

// Scratch (static device globals: allocation-free). fp16 stored as uint16_t.
__device__ uint16_t g_Q[Bq*Hq*Sq*HDq];    // [B,H,S,HD] fp16 (pre-scaled)
__device__ uint16_t g_K[Bq*Hq*Sq*HDq];    // [B,H,S,HD] fp16
__device__ uint16_t g_VT[Bq*Hq*HDq*Sq];   // [B,H,HD,S] fp16 (transposed V)
__device__ uint16_t g_ctx[Bq*Sq*Eq];      // [B,S,E] fp16
__device__ uint16_t g_qc[Mtot*Eq];        // fp16-rounded inputs
__device__ uint16_t g_kc[Mtot*Eq];
__device__ uint16_t g_vc[Mtot*Eq];
__device__ uint16_t g_wc[4][Eq*Eq];       // fp16-rounded weights

__device__ __forceinline__ uint32_t smem_u32(const void* p) {
    uint32_t a;
    asm("{ .reg .u64 t; cvta.to.shared.u64 t, %1; cvt.u32.u64 %0, t; }"
        : "=r"(a) : "l"(p));
    return a;
}

__device__ __forceinline__ void cp_async16(uint32_t dst, const void* src) {
    asm volatile("cp.async.cg.shared.global [%0], [%1], 16;"
                 :: "r"(dst), "l"(src));
}
#define CP_COMMIT()  asm volatile("cp.async.commit_group;" ::: "memory")
#define CP_WAIT1()   asm volatile("cp.async.wait_group 1;" ::: "memory")

__device__ __forceinline__ void ldsm4(uint32_t* r, uint32_t addr) {
    asm volatile("ldmatrix.sync.aligned.m8n8.x4.shared.b16 {%0,%1,%2,%3}, [%4];"
                 : "=r"(r[0]), "=r"(r[1]), "=r"(r[2]), "=r"(r[3]) : "r"(addr));
}

__device__ __forceinline__ void mma_f16(float c[4], const uint32_t a[4],
                                        const uint32_t b[2]) {
    asm volatile(
        "mma.sync.aligned.m16n8k16.row.col.f32.f16.f16.f32 "
        "{%0,%1,%2,%3}, {%4,%5,%6,%7}, {%8,%9}, {%0,%1,%2,%3};"
        : "+f"(c[0]), "+f"(c[1]), "+f"(c[2]), "+f"(c[3])
        : "r"(a[0]), "r"(a[1]), "r"(a[2]), "r"(a[3]), "r"(b[0]), "r"(b[1]));
}

__device__ __forceinline__ uint32_t pack_h2(float x, float y) {
    __half2 h = __floats2half2_rn(x, y);
    return *(uint32_t*)&h;
}

__device__ __forceinline__ float ex2(float x) {
    float r;
    asm("ex2.approx.f32 %0, %1;" : "=f"(r) : "f"(x));
    return r;
}

// ===========================================================================
// Single merged fp32 -> fp16 (RN) conversion pass over all 7 tensors.
// Flat float4 index: [0,3M4): q,k,v ; [3M4, 3M4+4W4): Wq,Wk,Wv,Wo.
// ===========================================================================
#define M4 (Mtot*Eq/4)        // 1048576 float4 per input tensor
#define W4 (Eq*Eq/4)          // 262144 float4 per weight tensor
#define CVT_TOTAL (3*M4 + 4*W4)

__global__ void __launch_bounds__(256)
cvt_all(const float4* __restrict__ q, const float4* __restrict__ k,
        const float4* __restrict__ v,
        const float4* __restrict__ Wq, const float4* __restrict__ Wk,
        const float4* __restrict__ Wv, const float4* __restrict__ Wo,
        uint2* __restrict__ dq, uint2* __restrict__ dk,
        uint2* __restrict__ dv, uint2* __restrict__ dw)
{
    int i = blockIdx.x * 256 + threadIdx.x;
    const float4* s;
    uint2* d;
    int off;
    if (i < 3*M4) {
        int t = i / M4; off = i - t*M4;
        s = t == 0 ? q : (t == 1 ? k : v);
        d = t == 0 ? dq : (t == 1 ? dk : dv);
    } else {
        int j = i - 3*M4;
        int t = j / W4; off = j - t*W4;
        s = t == 0 ? Wq : (t == 1 ? Wk : (t == 2 ? Wv : Wo));
        d = dw + (size_t)t * W4;
    }
    float4 val = s[off];
    d[off] = make_uint2(pack_h2(val.x, val.y), pack_h2(val.z, val.w));
}

// ===========================================================================
// GEMM core: one 128x128 tile of C = A @ W^T, K=1024, fp32 accum.
// 8 warps (2m x 4n), warp tile 64x32. cp.async 3-stage ring, K-stage = 64
// halves (16 stages, ONE __syncthreads per stage). Smem row stride 36 words
// (32 data + 4 pad; ldsm conflict-free as in attention).
// ===========================================================================
#define RSTRW 36
#define STAGE_W (128*RSTRW)                // 4608 words per operand-stage
#define GEMM_SMEM (6*STAGE_W*4)            // 3 stages x (A,W) = 110592 B
#define NSTG 16                            // 1024 / 64

__device__ __forceinline__ void gemm_core(
    const uint16_t* __restrict__ A, const uint16_t* __restrict__ W,
    uint32_t* smw, int m0, int n0, float c[4][4][4])
{
    const uint32_t smb = smem_u32(smw);
    const int tid  = threadIdx.x;
    const int wid  = tid >> 5;
    const int lane = tid & 31;
    const int wm   = (wid & 1) * 64;
    const int wn   = (wid >> 1) * 32;

    // staging: idx = tid + i*256 (i=0..3): row = idx>>3, chunk8 = idx&7
    const int r0 = tid >> 3;               // rows r0 + 32*i
    const int c8 = tid & 7;                // 8-half chunk within 64-half row

    const uint16_t* Ag = A + (size_t)(m0 + r0) * Eq + c8*8;
    const uint16_t* Wg = W + (size_t)(n0 + r0) * Eq + c8*8;
    const uint32_t sa = smb + (uint32_t)(r0*RSTRW + c8*4) * 4;
    const uint32_t sw = sa + STAGE_W * 4;

    const int arow = wm + (lane & 15);
    const int akw  = (lane >> 4) << 2;
    const int brow = wn + (lane & 7) + ((lane & 16) ? 8 : 0);
    const int bkw  = (lane & 8) ? 4 : 0;
    const uint32_t a_base = smb + (uint32_t)(arow*RSTRW + akw) * 4;
    const uint32_t b_base = smb + (uint32_t)(STAGE_W + brow*RSTRW + bkw) * 4;

#pragma unroll
    for (int mt = 0; mt < 4; ++mt)
#pragma unroll
        for (int nt = 0; nt < 4; ++nt)
#pragma unroll
            for (int r = 0; r < 4; ++r) c[mt][nt][r] = 0.f;

    // prologue: stages 0..1
#pragma unroll
    for (int p = 0; p < 2; ++p) {
        uint32_t so = (uint32_t)(p * 2 * STAGE_W * 4);
        int k0 = p * 64;
#pragma unroll
        for (int i = 0; i < 4; ++i) {
            cp_async16(sa + so + i*32*RSTRW*4, Ag + k0 + (size_t)i*32*Eq);
            cp_async16(sw + so + i*32*RSTRW*4, Wg + k0 + (size_t)i*32*Eq);
        }
        CP_COMMIT();
    }

    for (int s = 0; s < NSTG; ++s) {
        CP_WAIT1();          // stage s resident (s+1 in flight)
        __syncthreads();     // visible; all warps past stage s-1 compute

        // issue stage s+2 into buffer (s+2)%3 == (s-1)%3 (reads retired)
        if (s + 2 < NSTG) {
            uint32_t so = (uint32_t)(((s + 2) % 3) * 2 * STAGE_W * 4);
            int k0 = (s + 2) * 64;
#pragma unroll
            for (int i = 0; i < 4; ++i) {
                cp_async16(sa + so + i*32*RSTRW*4, Ag + k0 + (size_t)i*32*Eq);
                cp_async16(sw + so + i*32*RSTRW*4, Wg + k0 + (size_t)i*32*Eq);
            }
        }
        CP_COMMIT();         // always commit: 2 groups pending at loop top

        const uint32_t sofs = (uint32_t)((s % 3) * 2 * STAGE_W * 4);

#pragma unroll
        for (int s2 = 0; s2 < 4; ++s2) {   // four k16 slices per stage
            uint32_t af[4][4], bf[4][2];
#pragma unroll
            for (int ntp = 0; ntp < 2; ++ntp)
                ldsm4(bf[2*ntp], b_base + sofs +
                      (uint32_t)(ntp*16*RSTRW + s2*8) * 4);
#pragma unroll
            for (int mt = 0; mt < 4; ++mt)
                ldsm4(af[mt], a_base + sofs +
                      (uint32_t)(mt*16*RSTRW + s2*8) * 4);
#pragma unroll
            for (int mt = 0; mt < 4; ++mt)
#pragma unroll
                for (int nt = 0; nt < 4; ++nt)
                    mma_f16(c[mt][nt], af[mt], bf[nt]);
        }
    }
}

// ===========================================================================
// Merged QKV projection GEMM: grid.z = 0(Q)/1(K)/2(V-transposed).
// ===========================================================================
__global__ void __launch_bounds__(256, 2)
gemm_qkv(const uint16_t* __restrict__ qc, const uint16_t* __restrict__ kc,
         const uint16_t* __restrict__ vc, const uint16_t* __restrict__ wc,
         uint16_t* __restrict__ Qo, uint16_t* __restrict__ Ko,
         uint16_t* __restrict__ VTo)
{
    extern __shared__ uint32_t smw[];
    const int z = blockIdx.z;
    const uint16_t* A = z == 0 ? qc : (z == 1 ? kc : vc);
    const uint16_t* W = wc + (size_t)z * Eq * Eq;
    const float scale = (z == 0) ? QSCALE : 1.0f;
    const int m0 = blockIdx.y * 128;
    const int n0 = blockIdx.x * 128;

    float c[4][4][4];
    gemm_core(A, W, smw, m0, n0, c);

    const int tid  = threadIdx.x;
    const int wid  = tid >> 5;
    const int lane = tid & 31;
    const int g    = lane >> 2;
    const int tig  = lane & 3;
    const int wm   = (wid & 1) * 64;
    const int wn   = (wid >> 1) * 32;

#pragma unroll
    for (int mt = 0; mt < 4; ++mt) {
#pragma unroll
        for (int nt = 0; nt < 4; ++nt) {
            int row0 = m0 + wm + mt*16 + g;
            int col  = n0 + wn + nt*8 + 2*tig;
#pragma unroll
            for (int half = 0; half < 2; ++half) {
                int row = row0 + half*8;
                float v0 = c[mt][nt][half*2+0] * scale;
                float v1 = c[mt][nt][half*2+1] * scale;
                int b = row >> 10, s = row & 1023;
                int h = col >> 6, d = col & 63;
                if (z < 2) {
                    uint16_t* base = z == 0 ? Qo : Ko;
                    uint32_t* dst = (uint32_t*)(base +
                        ((((size_t)(b*Hq + h))*Sq + s)*HDq + d));
                    *dst = pack_h2(v0, v1);
                } else {
                    uint16_t* dst = VTo +
                        (((size_t)(b*Hq + h))*HDq + d)*Sq + s;
                    __half h0 = __float2half_rn(v0);
                    __half h1 = __float2half_rn(v1);
                    dst[0]  = *(uint16_t*)&h0;
                    dst[Sq] = *(uint16_t*)&h1;
                }
            }
        }
    }
}

// ===========================================================================
// Output projection GEMM: fp32 row-major straight to d_out.
// ===========================================================================
__global__ void __launch_bounds__(256, 2)
gemm_out(const uint16_t* __restrict__ A, const uint16_t* __restrict__ W,
         float* __restrict__ C)
{
    extern __shared__ uint32_t smw[];
    const int m0 = blockIdx.y * 128;
    const int n0 = blockIdx.x * 128;

    float c[4][4][4];
    gemm_core(A, W, smw, m0, n0, c);

    const int tid  = threadIdx.x;
    const int wid  = tid >> 5;
    const int lane = tid & 31;
    const int g    = lane >> 2;
    const int tig  = lane & 3;
    const int wm   = (wid & 1) * 64;
    const int wn   = (wid >> 1) * 32;

#pragma unroll
    for (int mt = 0; mt < 4; ++mt) {
#pragma unroll
        for (int nt = 0; nt < 4; ++nt) {
            int row0 = m0 + wm + mt*16 + g;
            int col  = n0 + wn + nt*8 + 2*tig;
#pragma unroll
            for (int half = 0; half < 2; ++half) {
                int row = row0 + half*8;
                float* dst = C + (size_t)row * Eq + col;
                *(float2*)dst = make_float2(c[mt][nt][half*2+0],
                                            c[mt][nt][half*2+1]);
            }
        }
    }
}

// ===========================================================================
// fp16 mma.sync flash attention (exp2 domain; Q pre-scaled by 1/8*log2e).
// Unchanged from R10 — at the legacy-HMMA roofline.
// ===========================================================================
#define QSTRW 36
#define TILE_W (64*QSTRW)
#define BUF_W (2*TILE_W)
#define PQ_W (128*QSTRW)
#define ATTN_SMEM ((2*BUF_W + PQ_W)*4)     // 55296 B

__global__ void __launch_bounds__(256, 2)
attn_h(const uint16_t* __restrict__ Qg, const uint16_t* __restrict__ Kg,
       const uint16_t* __restrict__ VTg, uint16_t* __restrict__ ctx)
{
    extern __shared__ uint32_t smw[];
    uint32_t* Pq = smw + 2*BUF_W;
    const uint32_t smb = smem_u32(smw);

    const int tid  = threadIdx.x;
    const int w    = tid >> 5;
    const int lane = tid & 31;
    const int g    = lane >> 2;
    const int tig  = lane & 3;
    const int qb = blockIdx.x, h = blockIdx.y, b = blockIdx.z;

    const uint16_t* Qp  = Qg  + (((size_t)(b*Hq + h))*Sq + qb*128) * HDq;
    const uint16_t* Kp  = Kg  + ((size_t)(b*Hq + h))*Sq*HDq;
    const uint16_t* VTp = VTg + ((size_t)(b*Hq + h))*HDq*Sq;

    auto issue_tile = [&](int kt) {
        uint32_t kb = smb + (uint32_t)((kt & 1) * BUF_W * 4);
        uint32_t vb = kb + TILE_W * 4;
#pragma unroll
        for (int i = 0; i < 2; ++i) {
            int idx = tid + i*256;
            int r = idx >> 3, c8 = idx & 7;
            uint32_t so = (uint32_t)((r*QSTRW + c8*4) * 4);
            cp_async16(kb + so, Kp + (size_t)(kt*64 + r)*HDq + c8*8);
            cp_async16(vb + so, VTp + (size_t)r*Sq + kt*64 + c8*8);
        }
    };

    issue_tile(0);
    CP_COMMIT();

    {
        const uint4* Q4 = (const uint4*)Qp;
#pragma unroll
        for (int i = 0; i < 4; ++i) {
            int idx = tid + i*256;
            int r = idx >> 3, c8 = idx & 7;
            *(uint4*)(Pq + r*QSTRW + c8*4) = Q4[idx];
        }
    }
    __syncthreads();

    uint32_t qf[4][4];
    {
        const int qrow = w*16 + (lane & 15);
        const uint32_t q_base = smb +
            (uint32_t)((2*BUF_W) + qrow*QSTRW + ((lane >> 4) << 2)) * 4;
#pragma unroll
        for (int s = 0; s < 4; ++s)
            ldsm4(qf[s], q_base + (uint32_t)(s*8) * 4);
    }

    const int kvrow = (lane & 7) + ((lane & 16) ? 8 : 0);
    const int kvkw  = (lane & 8) ? 4 : 0;
    const uint32_t kv_lane_off = (uint32_t)(kvrow*QSTRW + kvkw) * 4;

    float acc[8][4];
#pragma unroll
    for (int n = 0; n < 8; ++n)
#pragma unroll
        for (int r = 0; r < 4; ++r) acc[n][r] = 0.f;
    float m0 = -1e30f, m1 = -1e30f, l0 = 0.f, l1 = 0.f;

    for (int kt = 0; kt < 16; ++kt) {
        __syncthreads();
        if (kt + 1 < 16) issue_tile(kt + 1);
        CP_COMMIT();
        CP_WAIT1();
        __syncthreads();

        const uint32_t kbase = smb + (uint32_t)((kt & 1) * BUF_W * 4)
                             + kv_lane_off;
        const uint32_t vbase = kbase + (uint32_t)TILE_W * 4;

        float sc[8][4];
#pragma unroll
        for (int n = 0; n < 8; ++n)
#pragma unroll
            for (int r = 0; r < 4; ++r) sc[n][r] = 0.f;
#pragma unroll
        for (int s = 0; s < 4; ++s) {
            uint32_t kf[8][2];
#pragma unroll
            for (int ntp = 0; ntp < 4; ++ntp)
                ldsm4(kf[2*ntp], kbase + (uint32_t)(ntp*16*QSTRW + s*8) * 4);
#pragma unroll
            for (int n = 0; n < 8; ++n)
                mma_f16(sc[n], qf[s], kf[n]);
        }

        {
            float mx0 = -1e30f, mx1 = -1e30f;
#pragma unroll
            for (int n = 0; n < 8; ++n) {
                mx0 = fmaxf(mx0, fmaxf(sc[n][0], sc[n][1]));
                mx1 = fmaxf(mx1, fmaxf(sc[n][2], sc[n][3]));
            }
            mx0 = fmaxf(mx0, __shfl_xor_sync(0xffffffffu, mx0, 1));
            mx0 = fmaxf(mx0, __shfl_xor_sync(0xffffffffu, mx0, 2));
            mx1 = fmaxf(mx1, __shfl_xor_sync(0xffffffffu, mx1, 1));
            mx1 = fmaxf(mx1, __shfl_xor_sync(0xffffffffu, mx1, 2));
            float mn0 = fmaxf(m0, mx0), mn1 = fmaxf(m1, mx1);
            float a0 = ex2(m0 - mn0), a1 = ex2(m1 - mn1);
            m0 = mn0; m1 = mn1;
            float rs0 = 0.f, rs1 = 0.f;
#pragma unroll
            for (int n = 0; n < 8; ++n) {
                sc[n][0] = ex2(sc[n][0] - mn0);
                sc[n][1] = ex2(sc[n][1] - mn0);
                sc[n][2] = ex2(sc[n][2] - mn1);
                sc[n][3] = ex2(sc[n][3] - mn1);
                rs0 += sc[n][0] + sc[n][1];
                rs1 += sc[n][2] + sc[n][3];
            }
            rs0 += __shfl_xor_sync(0xffffffffu, rs0, 1);
            rs0 += __shfl_xor_sync(0xffffffffu, rs0, 2);
            rs1 += __shfl_xor_sync(0xffffffffu, rs1, 1);
            rs1 += __shfl_xor_sync(0xffffffffu, rs1, 2);
            l0 = l0*a0 + rs0;
            l1 = l1*a1 + rs1;
#pragma unroll
            for (int n = 0; n < 8; ++n) {
                acc[n][0] *= a0; acc[n][1] *= a0;
                acc[n][2] *= a1; acc[n][3] *= a1;
            }
        }

        uint32_t af[4][4];
#pragma unroll
        for (int s = 0; s < 4; ++s) {
            af[s][0] = pack_h2(sc[2*s  ][0], sc[2*s  ][1]);
            af[s][1] = pack_h2(sc[2*s  ][2], sc[2*s  ][3]);
            af[s][2] = pack_h2(sc[2*s+1][0], sc[2*s+1][1]);
            af[s][3] = pack_h2(sc[2*s+1][2], sc[2*s+1][3]);
        }

#pragma unroll
        for (int s = 0; s < 4; ++s) {
            uint32_t vf[8][2];
#pragma unroll
            for (int ntp = 0; ntp < 4; ++ntp)
                ldsm4(vf[2*ntp], vbase + (uint32_t)(ntp*16*QSTRW + s*8) * 4);
#pragma unroll
            for (int n = 0; n < 8; ++n)
                mma_f16(acc[n], af[s], vf[n]);
        }
    }

    float inv0 = 1.0f / l0, inv1 = 1.0f / l1;
    int row0 = qb*128 + w*16 + g;
#pragma unroll
    for (int n = 0; n < 8; ++n) {
        int e = h*64 + n*8 + 2*tig;
        uint32_t* d0 = (uint32_t*)(ctx + ((size_t)b*Sq + row0    )*Eq + e);
        uint32_t* d1 = (uint32_t*)(ctx + ((size_t)b*Sq + row0 + 8)*Eq + e);
        *d0 = pack_h2(acc[n][0]*inv0, acc[n][1]*inv0);
        *d1 = pack_h2(acc[n][2]*inv1, acc[n][3]*inv1);
    }
}

// ---------------------------------------------------------------------------
extern "C" void kernel_launch(void* const* d_in, const int* in_sizes, int n_in,
                              void* d_out, int out_size)
{
    const float* q  = (const float*)d_in[0];
    const float* k  = (const float*)d_in[1];
    const float* v  = (const float*)d_in[2];
    const float* Wq = (const float*)d_in[3];
    const float* Wk = (const float*)d_in[4];
    const float* Wv = (const float*)d_in[5];
    const float* Wo = (const float*)d_in[6];
    float* out = (float*)d_out;

    uint16_t *gQ, *gK, *gVT, *gctx, *gqc, *gkc, *gvc, *gwc;
    cudaGetSymbolAddress((void**)&gQ,   g_Q);
    cudaGetSymbolAddress((void**)&gK,   g_K);
    cudaGetSymbolAddress((void**)&gVT,  g_VT);
    cudaGetSymbolAddress((void**)&gctx, g_ctx);
    cudaGetSymbolAddress((void**)&gqc,  g_qc);
    cudaGetSymbolAddress((void**)&gkc,  g_kc);
    cudaGetSymbolAddress((void**)&gvc,  g_vc);
    cudaGetSymbolAddress((void**)&gwc,  g_wc);

    cudaFuncSetAttribute(gemm_qkv, cudaFuncAttributeMaxDynamicSharedMemorySize,
                         GEMM_SMEM);
    cudaFuncSetAttribute(gemm_out, cudaFuncAttributeMaxDynamicSharedMemorySize,
                         GEMM_SMEM);
    cudaFuncSetAttribute(attn_h, cudaFuncAttributeMaxDynamicSharedMemorySize,
                         ATTN_SMEM);

    // Single merged fp32->fp16 conversion (all inputs + weights)
    cvt_all<<<CVT_TOTAL/256, 256>>>(
        (const float4*)q, (const float4*)k, (const float4*)v,
        (const float4*)Wq, (const float4*)Wk, (const float4*)Wv,
        (const float4*)Wo,
        (uint2*)gqc, (uint2*)gkc, (uint2*)gvc, (uint2*)gwc);

    // Merged QKV projections: 768 CTAs in one launch
    gemm_qkv<<<dim3(Eq/128, Mtot/128, 3), 256, GEMM_SMEM>>>(
        gqc, gkc, gvc, gwc, gQ, gK, gVT);

    attn_h<<<dim3(Sq/128, Hq, Bq), 256, ATTN_SMEM>>>(gQ, gK, gVT, gctx);

    // Output projection straight into d_out (fp32)
    gemm_out<<<dim3(Eq/128, Mtot/128), 256, GEMM_SMEM>>>(
        gctx, gwc + 3*(size_t)Eq*Eq, out);
}